// round 1
// baseline (speedup 1.0000x reference)
#include <cuda_runtime.h>
#include <cuda_bf16.h>
#include <math.h>

// ---------------------------------------------------------------------------
// GCN_27797028339919: two-branch 2-layer GCN + root gather + fc + log_softmax
//
// Pipeline per branch (buffers A, B of [N,128] fp32):
//   A = X @ W1            (gemm, K=256)
//   B = dinv^2 * A        (self-loop init, replaces zeroing)
//   B += norm * A[src]    (edge scatter, red.global.add.v4.f32)
//   B = elu(B + b1)
//   A = B @ W2            (gemm, K=128)
//   B = dinv^2 * A ; scatter ; elu(B + b2)
//   roots_* = B[rootindex]
// Head: logits = [roots_td, roots_bu] @ fc_w + fc_b ; log_softmax
// ---------------------------------------------------------------------------

#define MAX_N 100000
#define MAX_R 2048

__device__ float g_A[(size_t)MAX_N * 128];
__device__ float g_B[(size_t)MAX_N * 128];
__device__ float g_dinv_td[MAX_N];
__device__ float g_dinv_bu[MAX_N];
__device__ float g_roots_td[(size_t)MAX_R * 128];
__device__ float g_roots_bu[(size_t)MAX_R * 128];

// ---------------- degree / dinv ----------------

__global__ void zero2_kernel(float* a, float* b, int n) {
    int i = blockIdx.x * blockDim.x + threadIdx.x;
    if (i < n) { a[i] = 0.f; b[i] = 0.f; }
}

__global__ void count2_kernel(const int* __restrict__ dst_a,
                              const int* __restrict__ dst_b,
                              float* da, float* db, int E) {
    int e = blockIdx.x * blockDim.x + threadIdx.x;
    if (e < E) {
        atomicAdd(&da[dst_a[e]], 1.0f);
        atomicAdd(&db[dst_b[e]], 1.0f);
    }
}

__global__ void dinv2_kernel(float* a, float* b, int n) {
    int i = blockIdx.x * blockDim.x + threadIdx.x;
    if (i < n) {
        a[i] = rsqrtf(a[i] + 1.0f);   // +1 self loop
        b[i] = rsqrtf(b[i] + 1.0f);
    }
}

// ---------------- GEMM: Y[M,128] = X[M,K] @ W[K,128] ----------------

template <int K>
__global__ __launch_bounds__(256)
void gemm_k(const float* __restrict__ X, const float* __restrict__ W,
            float* __restrict__ Y, int M) {
    __shared__ float xs[16][132];   // transposed: xs[k][row], padded (aligned for f4)
    __shared__ float ws[16][128];

    const int tid = threadIdx.x;
    const int row0 = blockIdx.x * 128;
    const int tx = tid & 15;        // 16 col groups of 8
    const int ty = tid >> 4;        // 16 row groups of 8

    float acc[8][8];
#pragma unroll
    for (int i = 0; i < 8; i++)
#pragma unroll
        for (int j = 0; j < 8; j++) acc[i][j] = 0.f;

    for (int k0 = 0; k0 < K; k0 += 16) {
#pragma unroll
        for (int l = 0; l < 2; l++) {
            int i = tid + l * 256;      // 512 float4 of X tile
            int r = i >> 2;             // 0..127
            int kq = (i & 3) << 2;      // 0,4,8,12
            int gr = row0 + r;
            float4 v = make_float4(0.f, 0.f, 0.f, 0.f);
            if (gr < M) v = *(const float4*)&X[(size_t)gr * K + k0 + kq];
            xs[kq + 0][r] = v.x; xs[kq + 1][r] = v.y;
            xs[kq + 2][r] = v.z; xs[kq + 3][r] = v.w;
        }
#pragma unroll
        for (int l = 0; l < 2; l++) {
            int i = tid + l * 256;      // 512 float4 of W tile
            int kr = i >> 5;            // 0..15
            int cq = (i & 31) << 2;     // 0..124
            *(float4*)&ws[kr][cq] = *(const float4*)&W[(size_t)(k0 + kr) * 128 + cq];
        }
        __syncthreads();

#pragma unroll
        for (int kk = 0; kk < 16; kk++) {
            float a[8], b[8];
            *(float4*)&a[0] = *(const float4*)&xs[kk][ty * 8];
            *(float4*)&a[4] = *(const float4*)&xs[kk][ty * 8 + 4];
            *(float4*)&b[0] = *(const float4*)&ws[kk][tx * 8];
            *(float4*)&b[4] = *(const float4*)&ws[kk][tx * 8 + 4];
#pragma unroll
            for (int i = 0; i < 8; i++)
#pragma unroll
                for (int j = 0; j < 8; j++)
                    acc[i][j] = fmaf(a[i], b[j], acc[i][j]);
        }
        __syncthreads();
    }

#pragma unroll
    for (int i = 0; i < 8; i++) {
        int gr = row0 + ty * 8 + i;
        if (gr < M) {
            *(float4*)&Y[(size_t)gr * 128 + tx * 8]     = *(float4*)&acc[i][0];
            *(float4*)&Y[(size_t)gr * 128 + tx * 8 + 4] = *(float4*)&acc[i][4];
        }
    }
}

// ---------------- self-loop init: out[i] = dinv[i]^2 * xw[i] ----------------

__global__ void init_self_kernel(const float* __restrict__ XW,
                                 const float* __restrict__ dinv,
                                 float* __restrict__ out, int n_chunks) {
    int i = blockIdx.x * blockDim.x + threadIdx.x;   // N*32 float4 chunks
    if (i >= n_chunks) return;
    int node = i >> 5;
    int c = (i & 31) << 2;
    float d = dinv[node];
    float nrm = d * d;
    float4 v = *(const float4*)&XW[(size_t)node * 128 + c];
    v.x *= nrm; v.y *= nrm; v.z *= nrm; v.w *= nrm;
    *(float4*)&out[(size_t)node * 128 + c] = v;
}

// ---------------- edge scatter: out[dst] += dinv[s]*dinv[d] * xw[src] -------

__global__ __launch_bounds__(256)
void scatter_kernel(const float* __restrict__ XW,
                    const int* __restrict__ src, const int* __restrict__ dst,
                    const float* __restrict__ dinv,
                    float* __restrict__ out, int E) {
    int gt = blockIdx.x * blockDim.x + threadIdx.x;
    int e = gt >> 5;
    int lane = gt & 31;
    if (e >= E) return;
    int s = __ldg(&src[e]);
    int d = __ldg(&dst[e]);
    float nrm = __ldg(&dinv[s]) * __ldg(&dinv[d]);
    float4 v = *(const float4*)&XW[(size_t)s * 128 + lane * 4];
    v.x *= nrm; v.y *= nrm; v.z *= nrm; v.w *= nrm;
    float* p = &out[(size_t)d * 128 + lane * 4];
    asm volatile("red.global.add.v4.f32 [%0], {%1,%2,%3,%4};"
                 :: "l"(p), "f"(v.x), "f"(v.y), "f"(v.z), "f"(v.w)
                 : "memory");
}

// ---------------- bias + ELU ----------------

__device__ __forceinline__ float elu1(float x) {
    return x > 0.f ? x : expm1f(x);
}

__global__ void bias_elu_kernel(float* __restrict__ buf,
                                const float* __restrict__ bias, int n_chunks) {
    int i = blockIdx.x * blockDim.x + threadIdx.x;   // N*32 float4 chunks
    if (i >= n_chunks) return;
    int c = (i & 31) << 2;
    float4 v = *(float4*)&buf[(size_t)i * 4];
    v.x = elu1(v.x + __ldg(&bias[c + 0]));
    v.y = elu1(v.y + __ldg(&bias[c + 1]));
    v.z = elu1(v.z + __ldg(&bias[c + 2]));
    v.w = elu1(v.w + __ldg(&bias[c + 3]));
    *(float4*)&buf[(size_t)i * 4] = v;
}

// ---------------- root gather ----------------

__global__ void gather_roots_kernel(const float* __restrict__ B,
                                    const int* __restrict__ roots,
                                    float* __restrict__ out, int n_chunks) {
    int i = blockIdx.x * blockDim.x + threadIdx.x;   // R*32 float4 chunks
    if (i >= n_chunks) return;
    int r = i >> 5;
    int c = (i & 31) << 2;
    int node = __ldg(&roots[r]);
    *(float4*)&out[(size_t)r * 128 + c] =
        *(const float4*)&B[(size_t)node * 128 + c];
}

// ---------------- head: fc + log_softmax ----------------

__global__ void head_kernel(const float* __restrict__ rt,
                            const float* __restrict__ rb,
                            const float* __restrict__ fcw,   // [256,4]
                            const float* __restrict__ fcb,   // [4]
                            float* __restrict__ out, int R) {
    int r = blockIdx.x * blockDim.x + threadIdx.x;
    if (r >= R) return;
    float acc0 = fcb[0], acc1 = fcb[1], acc2 = fcb[2], acc3 = fcb[3];
#pragma unroll 4
    for (int k = 0; k < 128; k++) {
        float f = rt[(size_t)r * 128 + k];
        const float* w = &fcw[(size_t)k * 4];
        acc0 = fmaf(f, w[0], acc0); acc1 = fmaf(f, w[1], acc1);
        acc2 = fmaf(f, w[2], acc2); acc3 = fmaf(f, w[3], acc3);
    }
#pragma unroll 4
    for (int k = 0; k < 128; k++) {
        float f = rb[(size_t)r * 128 + k];
        const float* w = &fcw[(size_t)(128 + k) * 4];
        acc0 = fmaf(f, w[0], acc0); acc1 = fmaf(f, w[1], acc1);
        acc2 = fmaf(f, w[2], acc2); acc3 = fmaf(f, w[3], acc3);
    }
    float m = fmaxf(fmaxf(acc0, acc1), fmaxf(acc2, acc3));
    float s = expf(acc0 - m) + expf(acc1 - m) + expf(acc2 - m) + expf(acc3 - m);
    float lse = m + logf(s);
    out[(size_t)r * 4 + 0] = acc0 - lse;
    out[(size_t)r * 4 + 1] = acc1 - lse;
    out[(size_t)r * 4 + 2] = acc2 - lse;
    out[(size_t)r * 4 + 3] = acc3 - lse;
}

// ---------------------------------------------------------------------------

static inline int ceil_div(int a, int b) { return (a + b - 1) / b; }

extern "C" void kernel_launch(void* const* d_in, const int* in_sizes, int n_in,
                              void* d_out, int out_size) {
    const float* x        = (const float*)d_in[0];   // [N,256]
    const int*   ei_td    = (const int*)d_in[1];     // [2,E]
    const int*   ei_bu    = (const int*)d_in[2];     // [2,E]
    const int*   rootidx  = (const int*)d_in[3];     // [R]
    const float* w1 = (const float*)d_in[4];
    const float* b1 = (const float*)d_in[5];
    const float* w2 = (const float*)d_in[6];
    const float* b2 = (const float*)d_in[7];
    const float* w3 = (const float*)d_in[8];
    const float* b3 = (const float*)d_in[9];
    const float* w4 = (const float*)d_in[10];
    const float* b4 = (const float*)d_in[11];
    const float* fcw = (const float*)d_in[12];
    const float* fcb = (const float*)d_in[13];
    float* out = (float*)d_out;

    const int N = in_sizes[0] / 256;
    const int E = in_sizes[1] / 2;
    const int R = in_sizes[3];

    const int* src_td = ei_td;
    const int* dst_td = ei_td + E;
    const int* src_bu = ei_bu;
    const int* dst_bu = ei_bu + E;

    float *A, *B, *dinv_td, *dinv_bu, *roots_td, *roots_bu;
    cudaGetSymbolAddress((void**)&A, g_A);
    cudaGetSymbolAddress((void**)&B, g_B);
    cudaGetSymbolAddress((void**)&dinv_td, g_dinv_td);
    cudaGetSymbolAddress((void**)&dinv_bu, g_dinv_bu);
    cudaGetSymbolAddress((void**)&roots_td, g_roots_td);
    cudaGetSymbolAddress((void**)&roots_bu, g_roots_bu);

    const int n_chunks = N * 32;      // float4 chunks over [N,128]
    const int r_chunks = R * 32;

    // --- degrees / dinv for both edge sets ---
    zero2_kernel<<<ceil_div(N, 256), 256>>>(dinv_td, dinv_bu, N);
    count2_kernel<<<ceil_div(E, 256), 256>>>(dst_td, dst_bu, dinv_td, dinv_bu, E);
    dinv2_kernel<<<ceil_div(N, 256), 256>>>(dinv_td, dinv_bu, N);

    const int gemm_blocks = ceil_div(N, 128);
    const int scat_blocks = ceil_div(E * 32, 256);
    const int ew_blocks   = ceil_div(n_chunks, 256);

    // ---------------- top-down branch ----------------
    gemm_k<256><<<gemm_blocks, 256>>>(x, w1, A, N);
    init_self_kernel<<<ew_blocks, 256>>>(A, dinv_td, B, n_chunks);
    scatter_kernel<<<scat_blocks, 256>>>(A, src_td, dst_td, dinv_td, B, E);
    bias_elu_kernel<<<ew_blocks, 256>>>(B, b1, n_chunks);

    gemm_k<128><<<gemm_blocks, 256>>>(B, w2, A, N);
    init_self_kernel<<<ew_blocks, 256>>>(A, dinv_td, B, n_chunks);
    scatter_kernel<<<scat_blocks, 256>>>(A, src_td, dst_td, dinv_td, B, E);
    bias_elu_kernel<<<ew_blocks, 256>>>(B, b2, n_chunks);

    gather_roots_kernel<<<ceil_div(r_chunks, 256), 256>>>(B, rootidx, roots_td, r_chunks);

    // ---------------- bottom-up branch ----------------
    gemm_k<256><<<gemm_blocks, 256>>>(x, w3, A, N);
    init_self_kernel<<<ew_blocks, 256>>>(A, dinv_bu, B, n_chunks);
    scatter_kernel<<<scat_blocks, 256>>>(A, src_bu, dst_bu, dinv_bu, B, E);
    bias_elu_kernel<<<ew_blocks, 256>>>(B, b3, n_chunks);

    gemm_k<128><<<gemm_blocks, 256>>>(B, w4, A, N);
    init_self_kernel<<<ew_blocks, 256>>>(A, dinv_bu, B, n_chunks);
    scatter_kernel<<<scat_blocks, 256>>>(A, src_bu, dst_bu, dinv_bu, B, E);
    bias_elu_kernel<<<ew_blocks, 256>>>(B, b4, n_chunks);

    gather_roots_kernel<<<ceil_div(r_chunks, 256), 256>>>(B, rootidx, roots_bu, r_chunks);

    // ---------------- head ----------------
    head_kernel<<<ceil_div(R, 128), 128>>>(roots_td, roots_bu, fcw, fcb, out, R);
}

// round 2
// speedup vs baseline: 1.7445x; 1.7445x over previous
#include <cuda_runtime.h>
#include <cuda_bf16.h>
#include <math.h>

// ---------------------------------------------------------------------------
// GCN_27797028339919 — round 2
//  * bucketed per-dst gather (no atomics in aggregation) with fused
//    self-loop + bias + ELU
//  * double-buffered 128x128 SIMT GEMM, dual-branch via blockIdx.y
// ---------------------------------------------------------------------------

#define MAX_N 100000
#define MAX_R 2048
#define SLOTS 64

__device__ float g_A_td[(size_t)MAX_N * 128];
__device__ float g_B_td[(size_t)MAX_N * 128];
__device__ float g_A_bu[(size_t)MAX_N * 128];
__device__ float g_B_bu[(size_t)MAX_N * 128];
__device__ int   g_cnt_td[MAX_N];
__device__ int   g_cnt_bu[MAX_N];
__device__ float g_dinv_td[MAX_N];
__device__ float g_dinv_bu[MAX_N];
__device__ int   g_srcs_td[(size_t)MAX_N * SLOTS];
__device__ int   g_srcs_bu[(size_t)MAX_N * SLOTS];
__device__ float g_roots_td[(size_t)MAX_R * 128];
__device__ float g_roots_bu[(size_t)MAX_R * 128];

static inline int ceil_div(int a, int b) { return (a + b - 1) / b; }

// ---------------- bucket build ----------------

__global__ void zero_cnt_kernel(int* a, int* b, int n) {
    int i = blockIdx.x * blockDim.x + threadIdx.x;
    if (i < n) { a[i] = 0; b[i] = 0; }
}

__global__ void fill_kernel(const int* __restrict__ src_td, const int* __restrict__ dst_td,
                            const int* __restrict__ src_bu, const int* __restrict__ dst_bu,
                            int* cnt_td, int* cnt_bu,
                            int* __restrict__ srcs_td, int* __restrict__ srcs_bu, int E) {
    int e = blockIdx.x * blockDim.x + threadIdx.x;
    if (e >= E) return;
    {
        int d = __ldg(&dst_td[e]);
        int p = atomicAdd(&cnt_td[d], 1);
        if (p < SLOTS) srcs_td[(size_t)d * SLOTS + p] = __ldg(&src_td[e]);
    }
    {
        int d = __ldg(&dst_bu[e]);
        int p = atomicAdd(&cnt_bu[d], 1);
        if (p < SLOTS) srcs_bu[(size_t)d * SLOTS + p] = __ldg(&src_bu[e]);
    }
}

__global__ void dinv_kernel(const int* ca, const int* cb, float* da, float* db, int n) {
    int i = blockIdx.x * blockDim.x + threadIdx.x;
    if (i < n) {
        da[i] = rsqrtf((float)ca[i] + 1.0f);   // +1 self loop
        db[i] = rsqrtf((float)cb[i] + 1.0f);
    }
}

// ---------------- GEMM: Y[M,128] = X[M,K] @ W[K,128], dual-branch ----------

template <int K>
__global__ __launch_bounds__(256)
void gemm_dual(const float* __restrict__ X0, const float* __restrict__ X1,
               const float* __restrict__ W0, const float* __restrict__ W1,
               float* __restrict__ Y0, float* __restrict__ Y1, int M) {
    const float* X = blockIdx.y ? X1 : X0;
    const float* W = blockIdx.y ? W1 : W0;
    float*       Y = blockIdx.y ? Y1 : Y0;

    __shared__ float xs[2][8][132];   // transposed [k][row], 132-stride: conflict-free
    __shared__ float ws[2][8][128];

    const int tid  = threadIdx.x;
    const int row0 = blockIdx.x * 128;
    const int tx = tid & 15;          // 16 col groups of 8
    const int ty = tid >> 4;          // 16 row groups of 8

    // loader mapping
    const int lrow = tid >> 1;        // X row within tile (0..127)
    const int lk   = (tid & 1) * 4;   // k sub-offset 0 or 4
    const int wk   = tid >> 5;        // W k-row (0..7)
    const int wc   = (tid & 31) * 4;  // W col

    const int grow = row0 + lrow;
    const bool xok = grow < M;

    float acc[8][8];
#pragma unroll
    for (int i = 0; i < 8; i++)
#pragma unroll
        for (int j = 0; j < 8; j++) acc[i][j] = 0.f;

    const int NK = K / 8;

    float4 xv = make_float4(0.f, 0.f, 0.f, 0.f);
    if (xok) xv = *(const float4*)&X[(size_t)grow * K + lk];
    float4 wv = *(const float4*)&W[(size_t)wk * 128 + wc];

    xs[0][lk + 0][lrow] = xv.x; xs[0][lk + 1][lrow] = xv.y;
    xs[0][lk + 2][lrow] = xv.z; xs[0][lk + 3][lrow] = xv.w;
    *(float4*)&ws[0][wk][wc] = wv;
    __syncthreads();

    for (int t = 0; t < NK; t++) {
        const int cur = t & 1;
        if (t + 1 < NK) {
            xv = make_float4(0.f, 0.f, 0.f, 0.f);
            if (xok) xv = *(const float4*)&X[(size_t)grow * K + (t + 1) * 8 + lk];
            wv = *(const float4*)&W[(size_t)((t + 1) * 8 + wk) * 128 + wc];
        }
#pragma unroll
        for (int kk = 0; kk < 8; kk++) {
            float a[8], b[8];
            *(float4*)&a[0] = *(const float4*)&xs[cur][kk][ty * 8];
            *(float4*)&a[4] = *(const float4*)&xs[cur][kk][ty * 8 + 4];
            *(float4*)&b[0] = *(const float4*)&ws[cur][kk][tx * 8];
            *(float4*)&b[4] = *(const float4*)&ws[cur][kk][tx * 8 + 4];
#pragma unroll
            for (int i = 0; i < 8; i++)
#pragma unroll
                for (int j = 0; j < 8; j++)
                    acc[i][j] = fmaf(a[i], b[j], acc[i][j]);
        }
        if (t + 1 < NK) {
            const int nxt = cur ^ 1;
            xs[nxt][lk + 0][lrow] = xv.x; xs[nxt][lk + 1][lrow] = xv.y;
            xs[nxt][lk + 2][lrow] = xv.z; xs[nxt][lk + 3][lrow] = xv.w;
            *(float4*)&ws[nxt][wk][wc] = wv;
            __syncthreads();
        }
    }

#pragma unroll
    for (int i = 0; i < 8; i++) {
        int gr = row0 + ty * 8 + i;
        if (gr < M) {
            *(float4*)&Y[(size_t)gr * 128 + tx * 8]     = *(float4*)&acc[i][0];
            *(float4*)&Y[(size_t)gr * 128 + tx * 8 + 4] = *(float4*)&acc[i][4];
        }
    }
}

// ---------------- aggregation: B = elu(bias + sum_norm*A[src] + dinv^2*A[d]) -

__device__ __forceinline__ float elu1(float x) {
    return x > 0.f ? x : expm1f(x);
}

__global__ __launch_bounds__(256)
void agg_dual(const float* __restrict__ A0, const float* __restrict__ A1,
              float* __restrict__ B0, float* __restrict__ B1,
              const int* __restrict__ cnt0, const int* __restrict__ cnt1,
              const int* __restrict__ srcs0, const int* __restrict__ srcs1,
              const float* __restrict__ dinv0, const float* __restrict__ dinv1,
              const float* __restrict__ bias0, const float* __restrict__ bias1,
              int N) {
    int node = (blockIdx.x * 256 + threadIdx.x) >> 5;
    if (node >= N) return;
    int lane = threadIdx.x & 31;

    const float* A;  float* B;  const int* cnt;  const int* srcs;
    const float* dinv;  const float* bias;
    if (blockIdx.y) { A = A1; B = B1; cnt = cnt1; srcs = srcs1; dinv = dinv1; bias = bias1; }
    else            { A = A0; B = B0; cnt = cnt0; srcs = srcs0; dinv = dinv0; bias = bias0; }

    const float dd = __ldg(&dinv[node]);
    float4 a = *(const float4*)&A[(size_t)node * 128 + lane * 4];
    float nrm = dd * dd;
    float4 acc = make_float4(nrm * a.x, nrm * a.y, nrm * a.z, nrm * a.w);

    int c = min(__ldg(&cnt[node]), SLOTS);
    const int* sp = &srcs[(size_t)node * SLOTS];

    int i = 0;
    for (; i + 4 <= c; i += 4) {
        int4 s4 = *(const int4*)&sp[i];
        float n0 = dd * __ldg(&dinv[s4.x]);
        float n1 = dd * __ldg(&dinv[s4.y]);
        float n2 = dd * __ldg(&dinv[s4.z]);
        float n3 = dd * __ldg(&dinv[s4.w]);
        float4 v0 = __ldg((const float4*)&A[(size_t)s4.x * 128 + lane * 4]);
        float4 v1 = __ldg((const float4*)&A[(size_t)s4.y * 128 + lane * 4]);
        float4 v2 = __ldg((const float4*)&A[(size_t)s4.z * 128 + lane * 4]);
        float4 v3 = __ldg((const float4*)&A[(size_t)s4.w * 128 + lane * 4]);
        acc.x = fmaf(n0, v0.x, acc.x); acc.y = fmaf(n0, v0.y, acc.y);
        acc.z = fmaf(n0, v0.z, acc.z); acc.w = fmaf(n0, v0.w, acc.w);
        acc.x = fmaf(n1, v1.x, acc.x); acc.y = fmaf(n1, v1.y, acc.y);
        acc.z = fmaf(n1, v1.z, acc.z); acc.w = fmaf(n1, v1.w, acc.w);
        acc.x = fmaf(n2, v2.x, acc.x); acc.y = fmaf(n2, v2.y, acc.y);
        acc.z = fmaf(n2, v2.z, acc.z); acc.w = fmaf(n2, v2.w, acc.w);
        acc.x = fmaf(n3, v3.x, acc.x); acc.y = fmaf(n3, v3.y, acc.y);
        acc.z = fmaf(n3, v3.z, acc.z); acc.w = fmaf(n3, v3.w, acc.w);
    }
    for (; i < c; i++) {
        int s = __ldg(&sp[i]);
        float n = dd * __ldg(&dinv[s]);
        float4 v = __ldg((const float4*)&A[(size_t)s * 128 + lane * 4]);
        acc.x = fmaf(n, v.x, acc.x); acc.y = fmaf(n, v.y, acc.y);
        acc.z = fmaf(n, v.z, acc.z); acc.w = fmaf(n, v.w, acc.w);
    }

    float4 bv = *(const float4*)&bias[lane * 4];
    acc.x = elu1(acc.x + bv.x);
    acc.y = elu1(acc.y + bv.y);
    acc.z = elu1(acc.z + bv.z);
    acc.w = elu1(acc.w + bv.w);
    *(float4*)&B[(size_t)node * 128 + lane * 4] = acc;
}

// ---------------- root gather ----------------

__global__ void gather_roots_kernel(const float* __restrict__ B,
                                    const int* __restrict__ roots,
                                    float* __restrict__ out, int n_chunks) {
    int i = blockIdx.x * blockDim.x + threadIdx.x;   // R*32 float4 chunks
    if (i >= n_chunks) return;
    int r = i >> 5;
    int c = (i & 31) << 2;
    int node = __ldg(&roots[r]);
    *(float4*)&out[(size_t)r * 128 + c] =
        *(const float4*)&B[(size_t)node * 128 + c];
}

// ---------------- head: fc + log_softmax ----------------

__global__ void head_kernel(const float* __restrict__ rt,
                            const float* __restrict__ rb,
                            const float* __restrict__ fcw,   // [256,4]
                            const float* __restrict__ fcb,   // [4]
                            float* __restrict__ out, int R) {
    int r = blockIdx.x * blockDim.x + threadIdx.x;
    if (r >= R) return;
    float acc0 = fcb[0], acc1 = fcb[1], acc2 = fcb[2], acc3 = fcb[3];
#pragma unroll 4
    for (int k = 0; k < 128; k++) {
        float f = rt[(size_t)r * 128 + k];
        const float* w = &fcw[(size_t)k * 4];
        acc0 = fmaf(f, w[0], acc0); acc1 = fmaf(f, w[1], acc1);
        acc2 = fmaf(f, w[2], acc2); acc3 = fmaf(f, w[3], acc3);
    }
#pragma unroll 4
    for (int k = 0; k < 128; k++) {
        float f = rb[(size_t)r * 128 + k];
        const float* w = &fcw[(size_t)(128 + k) * 4];
        acc0 = fmaf(f, w[0], acc0); acc1 = fmaf(f, w[1], acc1);
        acc2 = fmaf(f, w[2], acc2); acc3 = fmaf(f, w[3], acc3);
    }
    float m = fmaxf(fmaxf(acc0, acc1), fmaxf(acc2, acc3));
    float s = expf(acc0 - m) + expf(acc1 - m) + expf(acc2 - m) + expf(acc3 - m);
    float lse = m + logf(s);
    out[(size_t)r * 4 + 0] = acc0 - lse;
    out[(size_t)r * 4 + 1] = acc1 - lse;
    out[(size_t)r * 4 + 2] = acc2 - lse;
    out[(size_t)r * 4 + 3] = acc3 - lse;
}

// ---------------------------------------------------------------------------

extern "C" void kernel_launch(void* const* d_in, const int* in_sizes, int n_in,
                              void* d_out, int out_size) {
    const float* x       = (const float*)d_in[0];   // [N,256]
    const int*   ei_td   = (const int*)d_in[1];     // [2,E]
    const int*   ei_bu   = (const int*)d_in[2];     // [2,E]
    const int*   rootidx = (const int*)d_in[3];     // [R]
    const float* w1 = (const float*)d_in[4];
    const float* b1 = (const float*)d_in[5];
    const float* w2 = (const float*)d_in[6];
    const float* b2 = (const float*)d_in[7];
    const float* w3 = (const float*)d_in[8];
    const float* b3 = (const float*)d_in[9];
    const float* w4 = (const float*)d_in[10];
    const float* b4 = (const float*)d_in[11];
    const float* fcw = (const float*)d_in[12];
    const float* fcb = (const float*)d_in[13];
    float* out = (float*)d_out;

    const int N = in_sizes[0] / 256;
    const int E = in_sizes[1] / 2;
    const int R = in_sizes[3];

    const int* src_td = ei_td;
    const int* dst_td = ei_td + E;
    const int* src_bu = ei_bu;
    const int* dst_bu = ei_bu + E;

    float *A_td, *B_td, *A_bu, *B_bu, *dinv_td, *dinv_bu, *roots_td, *roots_bu;
    int *cnt_td, *cnt_bu, *srcs_td, *srcs_bu;
    cudaGetSymbolAddress((void**)&A_td, g_A_td);
    cudaGetSymbolAddress((void**)&B_td, g_B_td);
    cudaGetSymbolAddress((void**)&A_bu, g_A_bu);
    cudaGetSymbolAddress((void**)&B_bu, g_B_bu);
    cudaGetSymbolAddress((void**)&cnt_td, g_cnt_td);
    cudaGetSymbolAddress((void**)&cnt_bu, g_cnt_bu);
    cudaGetSymbolAddress((void**)&dinv_td, g_dinv_td);
    cudaGetSymbolAddress((void**)&dinv_bu, g_dinv_bu);
    cudaGetSymbolAddress((void**)&srcs_td, g_srcs_td);
    cudaGetSymbolAddress((void**)&srcs_bu, g_srcs_bu);
    cudaGetSymbolAddress((void**)&roots_td, g_roots_td);
    cudaGetSymbolAddress((void**)&roots_bu, g_roots_bu);

    // --- bucketed CSR + dinv ---
    zero_cnt_kernel<<<ceil_div(N, 256), 256>>>(cnt_td, cnt_bu, N);
    fill_kernel<<<ceil_div(E, 256), 256>>>(src_td, dst_td, src_bu, dst_bu,
                                           cnt_td, cnt_bu, srcs_td, srcs_bu, E);
    dinv_kernel<<<ceil_div(N, 256), 256>>>(cnt_td, cnt_bu, dinv_td, dinv_bu, N);

    const dim3 gemm_grid(ceil_div(N, 128), 2);
    const dim3 agg_grid(ceil_div(N, 8), 2);
    const int r_chunks = R * 32;

    // layer 1 (both branches)
    gemm_dual<256><<<gemm_grid, 256>>>(x, x, w1, w3, A_td, A_bu, N);
    agg_dual<<<agg_grid, 256>>>(A_td, A_bu, B_td, B_bu, cnt_td, cnt_bu,
                                srcs_td, srcs_bu, dinv_td, dinv_bu, b1, b3, N);
    // layer 2 (both branches)
    gemm_dual<128><<<gemm_grid, 256>>>(B_td, B_bu, w2, w4, A_td, A_bu, N);
    agg_dual<<<agg_grid, 256>>>(A_td, A_bu, B_td, B_bu, cnt_td, cnt_bu,
                                srcs_td, srcs_bu, dinv_td, dinv_bu, b2, b4, N);

    gather_roots_kernel<<<ceil_div(r_chunks, 256), 256>>>(B_td, rootidx, roots_td, r_chunks);
    gather_roots_kernel<<<ceil_div(r_chunks, 256), 256>>>(B_bu, rootidx, roots_bu, r_chunks);

    head_kernel<<<ceil_div(R, 128), 128>>>(roots_td, roots_bu, fcw, fcb, out, R);
}

// round 3
// speedup vs baseline: 2.8321x; 1.6235x over previous
#include <cuda_runtime.h>
#include <cuda_bf16.h>
#include <math.h>
#include <stdint.h>

// ---------------------------------------------------------------------------
// GCN_27797028339919 — round 3
//  * GEMMs moved to tf32 mma.sync tensor cores (fp32 accumulate)
//  * bucketed per-dst gather aggregation (no atomics), fused bias+ELU
// ---------------------------------------------------------------------------

#define MAX_N 100000
#define MAX_R 2048
#define SLOTS 64

__device__ float g_A_td[(size_t)MAX_N * 128];
__device__ float g_B_td[(size_t)MAX_N * 128];
__device__ float g_A_bu[(size_t)MAX_N * 128];
__device__ float g_B_bu[(size_t)MAX_N * 128];
__device__ int   g_cnt_td[MAX_N];
__device__ int   g_cnt_bu[MAX_N];
__device__ float g_dinv_td[MAX_N];
__device__ float g_dinv_bu[MAX_N];
__device__ int   g_srcs_td[(size_t)MAX_N * SLOTS];
__device__ int   g_srcs_bu[(size_t)MAX_N * SLOTS];
__device__ float g_roots_td[(size_t)MAX_R * 128];
__device__ float g_roots_bu[(size_t)MAX_R * 128];

static inline int ceil_div(int a, int b) { return (a + b - 1) / b; }

// ---------------- bucket build ----------------

__global__ void zero_cnt_kernel(int* a, int* b, int n) {
    int i = blockIdx.x * blockDim.x + threadIdx.x;
    if (i < n) { a[i] = 0; b[i] = 0; }
}

__global__ void fill_kernel(const int* __restrict__ src_td, const int* __restrict__ dst_td,
                            const int* __restrict__ src_bu, const int* __restrict__ dst_bu,
                            int* cnt_td, int* cnt_bu,
                            int* __restrict__ srcs_td, int* __restrict__ srcs_bu, int E) {
    int e = blockIdx.x * blockDim.x + threadIdx.x;
    if (e >= E) return;
    {
        int d = __ldg(&dst_td[e]);
        int p = atomicAdd(&cnt_td[d], 1);
        if (p < SLOTS) srcs_td[(size_t)d * SLOTS + p] = __ldg(&src_td[e]);
    }
    {
        int d = __ldg(&dst_bu[e]);
        int p = atomicAdd(&cnt_bu[d], 1);
        if (p < SLOTS) srcs_bu[(size_t)d * SLOTS + p] = __ldg(&src_bu[e]);
    }
}

__global__ void dinv_kernel(const int* ca, const int* cb, float* da, float* db, int n) {
    int i = blockIdx.x * blockDim.x + threadIdx.x;
    if (i < n) {
        da[i] = rsqrtf((float)ca[i] + 1.0f);   // +1 self loop
        db[i] = rsqrtf((float)cb[i] + 1.0f);
    }
}

// ---------------- tf32 helpers ----------------

__device__ __forceinline__ uint32_t f2tf32(float f) {
    uint32_t u;
    asm("cvt.rna.tf32.f32 %0, %1;" : "=r"(u) : "f"(f));
    return u;
}

__device__ __forceinline__ void mma_tf32(float* c, const uint32_t* a, const uint32_t* b) {
    asm volatile(
        "mma.sync.aligned.m16n8k8.row.col.f32.tf32.tf32.f32 "
        "{%0,%1,%2,%3}, {%4,%5,%6,%7}, {%8,%9}, {%0,%1,%2,%3};"
        : "+f"(c[0]), "+f"(c[1]), "+f"(c[2]), "+f"(c[3])
        : "r"(a[0]), "r"(a[1]), "r"(a[2]), "r"(a[3]),
          "r"(b[0]), "r"(b[1]));
}

// swizzled smem index for [k][m] tile, k<16, m<128.
// stride 136 (mod32=8) + XOR of bits 3..4 by (k>>2): conflict-free for
// transpose-stores, vec4-stores, and all fragment-load patterns.
__device__ __forceinline__ int sw_idx(int k, int m) {
    return k * 136 + (m ^ (((k >> 2) & 3) << 3));
}

// ---------------- GEMM: Y[M,128] = X[M,K] @ W[K,128], tf32 TC, dual-branch --

template <int K>
__global__ __launch_bounds__(256, 2)
void gemm_tc(const float* __restrict__ X0, const float* __restrict__ X1,
             const float* __restrict__ W0, const float* __restrict__ W1,
             float* __restrict__ Y0, float* __restrict__ Y1, int M) {
    const float* X = blockIdx.y ? X1 : X0;
    const float* W = blockIdx.y ? W1 : W0;
    float*       Y = blockIdx.y ? Y1 : Y0;

    __shared__ uint32_t xs[2][16 * 136];   // X tile, [k][m] transposed + swizzle
    __shared__ uint32_t ws[2][16 * 136];   // W tile, [k][n] + swizzle

    const int tid  = threadIdx.x;
    const int lane = tid & 31;
    const int wid  = tid >> 5;
    const int g    = lane >> 2;
    const int tig  = lane & 3;
    const int mbase = (wid & 1) * 64;
    const int nbase = (wid >> 1) * 32;
    const int row0  = blockIdx.x * 128;

    // loader mapping
    const int xr  = tid >> 2;          // X row within tile (+64 for l=1)
    const int xkq = (tid & 3) * 4;     // k sub-chunk
    const int wkr = tid >> 5;          // W k-row (+8 for l=1)
    const int wcq = (tid & 31) * 4;    // W col

    float c[4][4][4];
#pragma unroll
    for (int mf = 0; mf < 4; mf++)
#pragma unroll
        for (int nf = 0; nf < 4; nf++)
#pragma unroll
            for (int q = 0; q < 4; q++) c[mf][nf][q] = 0.f;

    float4 xv[2], wv[2];

    auto loadg = [&](int k0) {
#pragma unroll
        for (int l = 0; l < 2; l++) {
            int r = xr + l * 64;
            int grow = row0 + r;
            xv[l] = (grow < M) ? *(const float4*)&X[(size_t)grow * K + k0 + xkq]
                               : make_float4(0.f, 0.f, 0.f, 0.f);
            wv[l] = *(const float4*)&W[(size_t)(k0 + wkr + l * 8) * 128 + wcq];
        }
    };
    auto store_s = [&](int buf) {
#pragma unroll
        for (int l = 0; l < 2; l++) {
            int r = xr + l * 64;
            xs[buf][sw_idx(xkq + 0, r)] = f2tf32(xv[l].x);
            xs[buf][sw_idx(xkq + 1, r)] = f2tf32(xv[l].y);
            xs[buf][sw_idx(xkq + 2, r)] = f2tf32(xv[l].z);
            xs[buf][sw_idx(xkq + 3, r)] = f2tf32(xv[l].w);
            uint4 q = make_uint4(f2tf32(wv[l].x), f2tf32(wv[l].y),
                                 f2tf32(wv[l].z), f2tf32(wv[l].w));
            *(uint4*)&ws[buf][sw_idx(wkr + l * 8, wcq)] = q;
        }
    };
    auto compute = [&](int buf) {
#pragma unroll
        for (int ks = 0; ks < 2; ks++) {
            const int klo = ks * 8 + tig;
            const int khi = klo + 4;
            uint32_t a[4][4], b[4][2];
#pragma unroll
            for (int mf = 0; mf < 4; mf++) {
                int m0 = mbase + mf * 16 + g;
                a[mf][0] = xs[buf][sw_idx(klo, m0)];
                a[mf][1] = xs[buf][sw_idx(klo, m0 + 8)];
                a[mf][2] = xs[buf][sw_idx(khi, m0)];
                a[mf][3] = xs[buf][sw_idx(khi, m0 + 8)];
            }
#pragma unroll
            for (int nf = 0; nf < 4; nf++) {
                int n0 = nbase + nf * 8 + g;
                b[nf][0] = ws[buf][sw_idx(klo, n0)];
                b[nf][1] = ws[buf][sw_idx(khi, n0)];
            }
#pragma unroll
            for (int mf = 0; mf < 4; mf++)
#pragma unroll
                for (int nf = 0; nf < 4; nf++)
                    mma_tf32(c[mf][nf], a[mf], b[nf]);
        }
    };

    loadg(0);
    store_s(0);
    __syncthreads();

    const int NC = K / 16;
    for (int t = 0; t < NC; t++) {
        if (t + 1 < NC) loadg((t + 1) * 16);
        compute(t & 1);
        if (t + 1 < NC) {
            store_s((t + 1) & 1);
            __syncthreads();
        }
    }

    // epilogue
#pragma unroll
    for (int mf = 0; mf < 4; mf++) {
        int r0 = row0 + mbase + mf * 16 + g;
#pragma unroll
        for (int nf = 0; nf < 4; nf++) {
            int ncol = nbase + nf * 8 + tig * 2;
            if (r0 < M)
                *(float2*)&Y[(size_t)r0 * 128 + ncol] =
                    make_float2(c[mf][nf][0], c[mf][nf][1]);
            if (r0 + 8 < M)
                *(float2*)&Y[(size_t)(r0 + 8) * 128 + ncol] =
                    make_float2(c[mf][nf][2], c[mf][nf][3]);
        }
    }
}

// ---------------- aggregation: B = elu(bias + sum norm*A[src] + dinv^2*A[d]) -

__device__ __forceinline__ float elu1(float x) {
    return x > 0.f ? x : expm1f(x);
}

__global__ __launch_bounds__(256)
void agg_dual(const float* __restrict__ A0, const float* __restrict__ A1,
              float* __restrict__ B0, float* __restrict__ B1,
              const int* __restrict__ cnt0, const int* __restrict__ cnt1,
              const int* __restrict__ srcs0, const int* __restrict__ srcs1,
              const float* __restrict__ dinv0, const float* __restrict__ dinv1,
              const float* __restrict__ bias0, const float* __restrict__ bias1,
              int N) {
    int node = (blockIdx.x * 256 + threadIdx.x) >> 5;
    if (node >= N) return;
    int lane = threadIdx.x & 31;

    const float* A;  float* B;  const int* cnt;  const int* srcs;
    const float* dinv;  const float* bias;
    if (blockIdx.y) { A = A1; B = B1; cnt = cnt1; srcs = srcs1; dinv = dinv1; bias = bias1; }
    else            { A = A0; B = B0; cnt = cnt0; srcs = srcs0; dinv = dinv0; bias = bias0; }

    const float dd = __ldg(&dinv[node]);
    float4 a = *(const float4*)&A[(size_t)node * 128 + lane * 4];
    float nrm = dd * dd;
    float4 acc = make_float4(nrm * a.x, nrm * a.y, nrm * a.z, nrm * a.w);

    int c = min(__ldg(&cnt[node]), SLOTS);
    const int* sp = &srcs[(size_t)node * SLOTS];

    int i = 0;
    for (; i + 4 <= c; i += 4) {
        int4 s4 = *(const int4*)&sp[i];
        float n0 = dd * __ldg(&dinv[s4.x]);
        float n1 = dd * __ldg(&dinv[s4.y]);
        float n2 = dd * __ldg(&dinv[s4.z]);
        float n3 = dd * __ldg(&dinv[s4.w]);
        float4 v0 = __ldg((const float4*)&A[(size_t)s4.x * 128 + lane * 4]);
        float4 v1 = __ldg((const float4*)&A[(size_t)s4.y * 128 + lane * 4]);
        float4 v2 = __ldg((const float4*)&A[(size_t)s4.z * 128 + lane * 4]);
        float4 v3 = __ldg((const float4*)&A[(size_t)s4.w * 128 + lane * 4]);
        acc.x = fmaf(n0, v0.x, acc.x); acc.y = fmaf(n0, v0.y, acc.y);
        acc.z = fmaf(n0, v0.z, acc.z); acc.w = fmaf(n0, v0.w, acc.w);
        acc.x = fmaf(n1, v1.x, acc.x); acc.y = fmaf(n1, v1.y, acc.y);
        acc.z = fmaf(n1, v1.z, acc.z); acc.w = fmaf(n1, v1.w, acc.w);
        acc.x = fmaf(n2, v2.x, acc.x); acc.y = fmaf(n2, v2.y, acc.y);
        acc.z = fmaf(n2, v2.z, acc.z); acc.w = fmaf(n2, v2.w, acc.w);
        acc.x = fmaf(n3, v3.x, acc.x); acc.y = fmaf(n3, v3.y, acc.y);
        acc.z = fmaf(n3, v3.z, acc.z); acc.w = fmaf(n3, v3.w, acc.w);
    }
    for (; i < c; i++) {
        int s = __ldg(&sp[i]);
        float n = dd * __ldg(&dinv[s]);
        float4 v = __ldg((const float4*)&A[(size_t)s * 128 + lane * 4]);
        acc.x = fmaf(n, v.x, acc.x); acc.y = fmaf(n, v.y, acc.y);
        acc.z = fmaf(n, v.z, acc.z); acc.w = fmaf(n, v.w, acc.w);
    }

    float4 bv = *(const float4*)&bias[lane * 4];
    acc.x = elu1(acc.x + bv.x);
    acc.y = elu1(acc.y + bv.y);
    acc.z = elu1(acc.z + bv.z);
    acc.w = elu1(acc.w + bv.w);
    *(float4*)&B[(size_t)node * 128 + lane * 4] = acc;
}

// ---------------- root gather ----------------

__global__ void gather_roots_kernel(const float* __restrict__ B,
                                    const int* __restrict__ roots,
                                    float* __restrict__ out, int n_chunks) {
    int i = blockIdx.x * blockDim.x + threadIdx.x;   // R*32 float4 chunks
    if (i >= n_chunks) return;
    int r = i >> 5;
    int c = (i & 31) << 2;
    int node = __ldg(&roots[r]);
    *(float4*)&out[(size_t)r * 128 + c] =
        *(const float4*)&B[(size_t)node * 128 + c];
}

// ---------------- head: fc + log_softmax ----------------

__global__ void head_kernel(const float* __restrict__ rt,
                            const float* __restrict__ rb,
                            const float* __restrict__ fcw,   // [256,4]
                            const float* __restrict__ fcb,   // [4]
                            float* __restrict__ out, int R) {
    int r = blockIdx.x * blockDim.x + threadIdx.x;
    if (r >= R) return;
    float acc0 = fcb[0], acc1 = fcb[1], acc2 = fcb[2], acc3 = fcb[3];
#pragma unroll 4
    for (int k = 0; k < 128; k++) {
        float f = rt[(size_t)r * 128 + k];
        const float* w = &fcw[(size_t)k * 4];
        acc0 = fmaf(f, w[0], acc0); acc1 = fmaf(f, w[1], acc1);
        acc2 = fmaf(f, w[2], acc2); acc3 = fmaf(f, w[3], acc3);
    }
#pragma unroll 4
    for (int k = 0; k < 128; k++) {
        float f = rb[(size_t)r * 128 + k];
        const float* w = &fcw[(size_t)(128 + k) * 4];
        acc0 = fmaf(f, w[0], acc0); acc1 = fmaf(f, w[1], acc1);
        acc2 = fmaf(f, w[2], acc2); acc3 = fmaf(f, w[3], acc3);
    }
    float m = fmaxf(fmaxf(acc0, acc1), fmaxf(acc2, acc3));
    float s = expf(acc0 - m) + expf(acc1 - m) + expf(acc2 - m) + expf(acc3 - m);
    float lse = m + logf(s);
    out[(size_t)r * 4 + 0] = acc0 - lse;
    out[(size_t)r * 4 + 1] = acc1 - lse;
    out[(size_t)r * 4 + 2] = acc2 - lse;
    out[(size_t)r * 4 + 3] = acc3 - lse;
}

// ---------------------------------------------------------------------------

extern "C" void kernel_launch(void* const* d_in, const int* in_sizes, int n_in,
                              void* d_out, int out_size) {
    const float* x       = (const float*)d_in[0];   // [N,256]
    const int*   ei_td   = (const int*)d_in[1];     // [2,E]
    const int*   ei_bu   = (const int*)d_in[2];     // [2,E]
    const int*   rootidx = (const int*)d_in[3];     // [R]
    const float* w1 = (const float*)d_in[4];
    const float* b1 = (const float*)d_in[5];
    const float* w2 = (const float*)d_in[6];
    const float* b2 = (const float*)d_in[7];
    const float* w3 = (const float*)d_in[8];
    const float* b3 = (const float*)d_in[9];
    const float* w4 = (const float*)d_in[10];
    const float* b4 = (const float*)d_in[11];
    const float* fcw = (const float*)d_in[12];
    const float* fcb = (const float*)d_in[13];
    float* out = (float*)d_out;

    const int N = in_sizes[0] / 256;
    const int E = in_sizes[1] / 2;
    const int R = in_sizes[3];

    const int* src_td = ei_td;
    const int* dst_td = ei_td + E;
    const int* src_bu = ei_bu;
    const int* dst_bu = ei_bu + E;

    float *A_td, *B_td, *A_bu, *B_bu, *dinv_td, *dinv_bu, *roots_td, *roots_bu;
    int *cnt_td, *cnt_bu, *srcs_td, *srcs_bu;
    cudaGetSymbolAddress((void**)&A_td, g_A_td);
    cudaGetSymbolAddress((void**)&B_td, g_B_td);
    cudaGetSymbolAddress((void**)&A_bu, g_A_bu);
    cudaGetSymbolAddress((void**)&B_bu, g_B_bu);
    cudaGetSymbolAddress((void**)&cnt_td, g_cnt_td);
    cudaGetSymbolAddress((void**)&cnt_bu, g_cnt_bu);
    cudaGetSymbolAddress((void**)&dinv_td, g_dinv_td);
    cudaGetSymbolAddress((void**)&dinv_bu, g_dinv_bu);
    cudaGetSymbolAddress((void**)&srcs_td, g_srcs_td);
    cudaGetSymbolAddress((void**)&srcs_bu, g_srcs_bu);
    cudaGetSymbolAddress((void**)&roots_td, g_roots_td);
    cudaGetSymbolAddress((void**)&roots_bu, g_roots_bu);

    // --- bucketed CSR + dinv ---
    zero_cnt_kernel<<<ceil_div(N, 256), 256>>>(cnt_td, cnt_bu, N);
    fill_kernel<<<ceil_div(E, 256), 256>>>(src_td, dst_td, src_bu, dst_bu,
                                           cnt_td, cnt_bu, srcs_td, srcs_bu, E);
    dinv_kernel<<<ceil_div(N, 256), 256>>>(cnt_td, cnt_bu, dinv_td, dinv_bu, N);

    const dim3 gemm_grid(ceil_div(N, 128), 2);
    const dim3 agg_grid(ceil_div(N, 8), 2);
    const int r_chunks = R * 32;

    // layer 1 (both branches)
    gemm_tc<256><<<gemm_grid, 256>>>(x, x, w1, w3, A_td, A_bu, N);
    agg_dual<<<agg_grid, 256>>>(A_td, A_bu, B_td, B_bu, cnt_td, cnt_bu,
                                srcs_td, srcs_bu, dinv_td, dinv_bu, b1, b3, N);
    // layer 2 (both branches)
    gemm_tc<128><<<gemm_grid, 256>>>(B_td, B_bu, w2, w4, A_td, A_bu, N);
    agg_dual<<<agg_grid, 256>>>(A_td, A_bu, B_td, B_bu, cnt_td, cnt_bu,
                                srcs_td, srcs_bu, dinv_td, dinv_bu, b2, b4, N);

    gather_roots_kernel<<<ceil_div(r_chunks, 256), 256>>>(B_td, rootidx, roots_td, r_chunks);
    gather_roots_kernel<<<ceil_div(r_chunks, 256), 256>>>(B_bu, rootidx, roots_bu, r_chunks);

    head_kernel<<<ceil_div(R, 128), 128>>>(roots_td, roots_bu, fcw, fcb, out, R);
}

// round 5
// speedup vs baseline: 3.2545x; 1.1492x over previous
#include <cuda_runtime.h>
#include <cuda_fp16.h>
#include <math.h>
#include <stdint.h>

// ---------------------------------------------------------------------------
// GCN_27797028339919 — round 5 (round-4 design, compile fix)
//  * fp16 datapath: x/A/B stored as half2, fp16 mma m16n8k16 (fp32 accum)
//  * bucketed per-dst gather aggregation (no atomics), fused bias+ELU
// ---------------------------------------------------------------------------

#define MAX_N 100000
#define MAX_R 2048
#define SLOTS 64

// half2-packed buffers: [N][64] uint32 == [N][128] half
__device__ uint32_t g_A_td[(size_t)MAX_N * 64];
__device__ uint32_t g_B_td[(size_t)MAX_N * 64];
__device__ uint32_t g_A_bu[(size_t)MAX_N * 64];
__device__ uint32_t g_B_bu[(size_t)MAX_N * 64];
__device__ uint32_t g_xh[(size_t)MAX_N * 128];       // x as half2: [N][128] u32
__device__ uint32_t g_wh[(size_t)384 * 128];         // packed weights (pair-major)
__device__ int   g_cnt_td[MAX_N];
__device__ int   g_cnt_bu[MAX_N];
__device__ float g_dinv_td[MAX_N];
__device__ float g_dinv_bu[MAX_N];
__device__ int   g_srcs_td[(size_t)MAX_N * SLOTS];
__device__ int   g_srcs_bu[(size_t)MAX_N * SLOTS];
__device__ float g_roots_td[(size_t)MAX_R * 128];
__device__ float g_roots_bu[(size_t)MAX_R * 128];

static inline int ceil_div(int a, int b) { return (a + b - 1) / b; }

// ---------------- bit-cast helpers (compile fix) ----------------

__device__ __forceinline__ uint32_t h2_u32(__half2 h) {
    return *reinterpret_cast<uint32_t*>(&h);
}
__device__ __forceinline__ __half2 u32_h2(uint32_t u) {
    return *reinterpret_cast<__half2*>(&u);
}

// ---------------- conversions ----------------

__global__ void convert_x_kernel(const float* __restrict__ x,
                                 uint32_t* __restrict__ xh, int n4) {
    int i = blockIdx.x * blockDim.x + threadIdx.x;   // float4 chunks
    if (i >= n4) return;
    float4 v = *(const float4*)&x[(size_t)i * 4];
    uint2 o;
    o.x = h2_u32(__floats2half2_rn(v.x, v.y));
    o.y = h2_u32(__floats2half2_rn(v.z, v.w));
    *(uint2*)&xh[(size_t)i * 2] = o;
}

// pack weights: wh[prow][n] = half2(w[2p][n], w[2p+1][n])
// prow ranges: w1 0..127 (K=256), w2 128..191 (K=128), w3 192..319, w4 320..383
__global__ void pack_w_kernel(const float* __restrict__ w1, const float* __restrict__ w2,
                              const float* __restrict__ w3, const float* __restrict__ w4,
                              uint32_t* __restrict__ wh) {
    int i = blockIdx.x * blockDim.x + threadIdx.x;
    if (i >= 384 * 128) return;
    int prow = i >> 7;
    int n = i & 127;
    const float* w; int p;
    if (prow < 128)      { w = w1; p = prow; }
    else if (prow < 192) { w = w2; p = prow - 128; }
    else if (prow < 320) { w = w3; p = prow - 192; }
    else                 { w = w4; p = prow - 320; }
    float a = w[(size_t)(2 * p) * 128 + n];
    float b = w[(size_t)(2 * p + 1) * 128 + n];
    wh[i] = h2_u32(__floats2half2_rn(a, b));
}

// ---------------- bucket build ----------------

__global__ void zero_cnt_kernel(int* a, int* b, int n) {
    int i = blockIdx.x * blockDim.x + threadIdx.x;
    if (i < n) { a[i] = 0; b[i] = 0; }
}

__global__ void fill_kernel(const int* __restrict__ src_td, const int* __restrict__ dst_td,
                            const int* __restrict__ src_bu, const int* __restrict__ dst_bu,
                            int* cnt_td, int* cnt_bu,
                            int* __restrict__ srcs_td, int* __restrict__ srcs_bu, int E) {
    int e = blockIdx.x * blockDim.x + threadIdx.x;
    if (e >= E) return;
    {
        int d = __ldg(&dst_td[e]);
        int p = atomicAdd(&cnt_td[d], 1);
        if (p < SLOTS) srcs_td[(size_t)d * SLOTS + p] = __ldg(&src_td[e]);
    }
    {
        int d = __ldg(&dst_bu[e]);
        int p = atomicAdd(&cnt_bu[d], 1);
        if (p < SLOTS) srcs_bu[(size_t)d * SLOTS + p] = __ldg(&src_bu[e]);
    }
}

__global__ void dinv_kernel(const int* ca, const int* cb, float* da, float* db, int n) {
    int i = blockIdx.x * blockDim.x + threadIdx.x;
    if (i < n) {
        da[i] = rsqrtf((float)ca[i] + 1.0f);   // +1 self loop
        db[i] = rsqrtf((float)cb[i] + 1.0f);
    }
}

// ---------------- fp16 mma helpers ----------------

__device__ __forceinline__ void mma_f16(float* c, const uint32_t* a, const uint32_t* b) {
    asm volatile(
        "mma.sync.aligned.m16n8k16.row.col.f32.f16.f16.f32 "
        "{%0,%1,%2,%3}, {%4,%5,%6,%7}, {%8,%9}, {%0,%1,%2,%3};"
        : "+f"(c[0]), "+f"(c[1]), "+f"(c[2]), "+f"(c[3])
        : "r"(a[0]), "r"(a[1]), "r"(a[2]), "r"(a[3]),
          "r"(b[0]), "r"(b[1]));
}

// swizzled smem index for [pair][m] tile, pair<16, m<128 (32-bit elements)
__device__ __forceinline__ int sw_idx(int k, int m) {
    return k * 136 + (m ^ (((k >> 2) & 3) << 3));
}

// ---------------- GEMM: Y[M,128] = X[M,K] @ W[K,128], fp16 TC, dual ---------
// X: half2-packed, row stride K/2 u32.  W: packed [K/2][128] u32.
// Y: half2-packed [M][64] u32.

template <int K>
__global__ __launch_bounds__(256, 2)
void gemm_tc(const uint32_t* __restrict__ X0, const uint32_t* __restrict__ X1,
             const uint32_t* __restrict__ W0, const uint32_t* __restrict__ W1,
             uint32_t* __restrict__ Y0, uint32_t* __restrict__ Y1, int M) {
    const uint32_t* X = blockIdx.y ? X1 : X0;
    const uint32_t* W = blockIdx.y ? W1 : W0;
    uint32_t*       Y = blockIdx.y ? Y1 : Y0;

    constexpr int K2 = K / 2;          // pairs per row
    constexpr int NC = K / 32;         // k-tiles (32 halves = 16 pairs each)

    __shared__ uint32_t xs[2][16 * 136];   // X tile, [pair][m] + swizzle
    __shared__ uint32_t ws[2][16 * 136];   // W tile, [pair][n] + swizzle

    const int tid  = threadIdx.x;
    const int lane = tid & 31;
    const int wid  = tid >> 5;
    const int g    = lane >> 2;
    const int tig  = lane & 3;
    const int mbase = (wid & 1) * 64;
    const int nbase = (wid >> 1) * 32;
    const int row0  = blockIdx.x * 128;

    // loader mapping
    const int xr  = tid >> 2;          // X row within tile (+64 for l=1)
    const int xkq = (tid & 3) * 4;     // pair sub-chunk (0,4,8,12)
    const int wkr = tid >> 5;          // W pair-row (+8 for l=1)
    const int wcq = (tid & 31) * 4;    // W col

    float c[4][4][4];
#pragma unroll
    for (int mf = 0; mf < 4; mf++)
#pragma unroll
        for (int nf = 0; nf < 4; nf++)
#pragma unroll
            for (int q = 0; q < 4; q++) c[mf][nf][q] = 0.f;

    uint4 xv[2], wv[2];

    auto loadg = [&](int t) {
        const int p0 = t * 16;
#pragma unroll
        for (int l = 0; l < 2; l++) {
            int r = xr + l * 64;
            int grow = row0 + r;
            xv[l] = (grow < M) ? *(const uint4*)&X[(size_t)grow * K2 + p0 + xkq]
                               : make_uint4(0u, 0u, 0u, 0u);
            wv[l] = *(const uint4*)&W[(size_t)(p0 + wkr + l * 8) * 128 + wcq];
        }
    };
    auto store_s = [&](int buf) {
#pragma unroll
        for (int l = 0; l < 2; l++) {
            int r = xr + l * 64;
            xs[buf][sw_idx(xkq + 0, r)] = xv[l].x;
            xs[buf][sw_idx(xkq + 1, r)] = xv[l].y;
            xs[buf][sw_idx(xkq + 2, r)] = xv[l].z;
            xs[buf][sw_idx(xkq + 3, r)] = xv[l].w;
            *(uint4*)&ws[buf][sw_idx(wkr + l * 8, wcq)] = wv[l];
        }
    };
    auto compute = [&](int buf) {
#pragma unroll
        for (int ks = 0; ks < 2; ks++) {
            const int klo = ks * 8 + tig;      // pair index
            const int khi = klo + 4;
            uint32_t a[4][4], b[4][2];
#pragma unroll
            for (int mf = 0; mf < 4; mf++) {
                int m0 = mbase + mf * 16 + g;
                a[mf][0] = xs[buf][sw_idx(klo, m0)];
                a[mf][1] = xs[buf][sw_idx(klo, m0 + 8)];
                a[mf][2] = xs[buf][sw_idx(khi, m0)];
                a[mf][3] = xs[buf][sw_idx(khi, m0 + 8)];
            }
#pragma unroll
            for (int nf = 0; nf < 4; nf++) {
                int n0 = nbase + nf * 8 + g;
                b[nf][0] = ws[buf][sw_idx(klo, n0)];
                b[nf][1] = ws[buf][sw_idx(khi, n0)];
            }
#pragma unroll
            for (int mf = 0; mf < 4; mf++)
#pragma unroll
                for (int nf = 0; nf < 4; nf++)
                    mma_f16(c[mf][nf], a[mf], b[nf]);
        }
    };

    loadg(0);
    store_s(0);
    __syncthreads();

    for (int t = 0; t < NC; t++) {
        if (t + 1 < NC) loadg(t + 1);
        compute(t & 1);
        if (t + 1 < NC) {
            store_s((t + 1) & 1);
            __syncthreads();
        }
    }

    // epilogue: store half2 pairs
#pragma unroll
    for (int mf = 0; mf < 4; mf++) {
        int r0 = row0 + mbase + mf * 16 + g;
#pragma unroll
        for (int nf = 0; nf < 4; nf++) {
            int np = (nbase + nf * 8 + tig * 2) >> 1;    // half2 column
            if (r0 < M)
                Y[(size_t)r0 * 64 + np] =
                    h2_u32(__floats2half2_rn(c[mf][nf][0], c[mf][nf][1]));
            if (r0 + 8 < M)
                Y[(size_t)(r0 + 8) * 64 + np] =
                    h2_u32(__floats2half2_rn(c[mf][nf][2], c[mf][nf][3]));
        }
    }
}

// ---------------- aggregation: B = elu(bias + sum norm*A[src] + dinv^2*A[d]) -

__device__ __forceinline__ float elu1(float x) {
    return x > 0.f ? x : expm1f(x);
}

__device__ __forceinline__ float4 h4_to_f4(uint2 v) {
    float2 lo = __half22float2(u32_h2(v.x));
    float2 hi = __half22float2(u32_h2(v.y));
    return make_float4(lo.x, lo.y, hi.x, hi.y);
}

__global__ __launch_bounds__(256)
void agg_dual(const uint32_t* __restrict__ A0, const uint32_t* __restrict__ A1,
              uint32_t* __restrict__ B0, uint32_t* __restrict__ B1,
              const int* __restrict__ cnt0, const int* __restrict__ cnt1,
              const int* __restrict__ srcs0, const int* __restrict__ srcs1,
              const float* __restrict__ dinv0, const float* __restrict__ dinv1,
              const float* __restrict__ bias0, const float* __restrict__ bias1,
              int N) {
    int node = (blockIdx.x * 256 + threadIdx.x) >> 5;
    if (node >= N) return;
    int lane = threadIdx.x & 31;

    const uint32_t* A;  uint32_t* B;  const int* cnt;  const int* srcs;
    const float* dinv;  const float* bias;
    if (blockIdx.y) { A = A1; B = B1; cnt = cnt1; srcs = srcs1; dinv = dinv1; bias = bias1; }
    else            { A = A0; B = B0; cnt = cnt0; srcs = srcs0; dinv = dinv0; bias = bias0; }

    const uint2* A2 = (const uint2*)A;      // [N][32] uint2 (4 halves each)

    const float dd = __ldg(&dinv[node]);
    float4 a = h4_to_f4(A2[(size_t)node * 32 + lane]);
    float nrm = dd * dd;
    float4 acc = make_float4(nrm * a.x, nrm * a.y, nrm * a.z, nrm * a.w);

    int c = min(__ldg(&cnt[node]), SLOTS);
    const int* sp = &srcs[(size_t)node * SLOTS];

    int i = 0;
    for (; i + 4 <= c; i += 4) {
        int4 s4 = *(const int4*)&sp[i];
        float n0 = dd * __ldg(&dinv[s4.x]);
        float n1 = dd * __ldg(&dinv[s4.y]);
        float n2 = dd * __ldg(&dinv[s4.z]);
        float n3 = dd * __ldg(&dinv[s4.w]);
        float4 v0 = h4_to_f4(__ldg(&A2[(size_t)s4.x * 32 + lane]));
        float4 v1 = h4_to_f4(__ldg(&A2[(size_t)s4.y * 32 + lane]));
        float4 v2 = h4_to_f4(__ldg(&A2[(size_t)s4.z * 32 + lane]));
        float4 v3 = h4_to_f4(__ldg(&A2[(size_t)s4.w * 32 + lane]));
        acc.x = fmaf(n0, v0.x, acc.x); acc.y = fmaf(n0, v0.y, acc.y);
        acc.z = fmaf(n0, v0.z, acc.z); acc.w = fmaf(n0, v0.w, acc.w);
        acc.x = fmaf(n1, v1.x, acc.x); acc.y = fmaf(n1, v1.y, acc.y);
        acc.z = fmaf(n1, v1.z, acc.z); acc.w = fmaf(n1, v1.w, acc.w);
        acc.x = fmaf(n2, v2.x, acc.x); acc.y = fmaf(n2, v2.y, acc.y);
        acc.z = fmaf(n2, v2.z, acc.z); acc.w = fmaf(n2, v2.w, acc.w);
        acc.x = fmaf(n3, v3.x, acc.x); acc.y = fmaf(n3, v3.y, acc.y);
        acc.z = fmaf(n3, v3.z, acc.z); acc.w = fmaf(n3, v3.w, acc.w);
    }
    for (; i < c; i++) {
        int s = __ldg(&sp[i]);
        float n = dd * __ldg(&dinv[s]);
        float4 v = h4_to_f4(__ldg(&A2[(size_t)s * 32 + lane]));
        acc.x = fmaf(n, v.x, acc.x); acc.y = fmaf(n, v.y, acc.y);
        acc.z = fmaf(n, v.z, acc.z); acc.w = fmaf(n, v.w, acc.w);
    }

    float4 bv = *(const float4*)&bias[lane * 4];
    acc.x = elu1(acc.x + bv.x);
    acc.y = elu1(acc.y + bv.y);
    acc.z = elu1(acc.z + bv.z);
    acc.w = elu1(acc.w + bv.w);

    uint2 o;
    o.x = h2_u32(__floats2half2_rn(acc.x, acc.y));
    o.y = h2_u32(__floats2half2_rn(acc.z, acc.w));
    ((uint2*)B)[(size_t)node * 32 + lane] = o;
}

// ---------------- root gather (fp16 in -> fp32 out) ----------------

__global__ void gather_roots_kernel(const uint32_t* __restrict__ B,
                                    const int* __restrict__ roots,
                                    float* __restrict__ out, int n_chunks) {
    int i = blockIdx.x * blockDim.x + threadIdx.x;   // R*32 chunks of 4 vals
    if (i >= n_chunks) return;
    int r = i >> 5;
    int c = i & 31;
    int node = __ldg(&roots[r]);
    float4 v = h4_to_f4(((const uint2*)B)[(size_t)node * 32 + c]);
    *(float4*)&out[(size_t)r * 128 + c * 4] = v;
}

// ---------------- head: fc + log_softmax ----------------

__global__ void head_kernel(const float* __restrict__ rt,
                            const float* __restrict__ rb,
                            const float* __restrict__ fcw,   // [256,4]
                            const float* __restrict__ fcb,   // [4]
                            float* __restrict__ out, int R) {
    int r = blockIdx.x * blockDim.x + threadIdx.x;
    if (r >= R) return;
    float acc0 = fcb[0], acc1 = fcb[1], acc2 = fcb[2], acc3 = fcb[3];
#pragma unroll 4
    for (int k = 0; k < 128; k++) {
        float f = rt[(size_t)r * 128 + k];
        const float* w = &fcw[(size_t)k * 4];
        acc0 = fmaf(f, w[0], acc0); acc1 = fmaf(f, w[1], acc1);
        acc2 = fmaf(f, w[2], acc2); acc3 = fmaf(f, w[3], acc3);
    }
#pragma unroll 4
    for (int k = 0; k < 128; k++) {
        float f = rb[(size_t)r * 128 + k];
        const float* w = &fcw[(size_t)(128 + k) * 4];
        acc0 = fmaf(f, w[0], acc0); acc1 = fmaf(f, w[1], acc1);
        acc2 = fmaf(f, w[2], acc2); acc3 = fmaf(f, w[3], acc3);
    }
    float m = fmaxf(fmaxf(acc0, acc1), fmaxf(acc2, acc3));
    float s = expf(acc0 - m) + expf(acc1 - m) + expf(acc2 - m) + expf(acc3 - m);
    float lse = m + logf(s);
    out[(size_t)r * 4 + 0] = acc0 - lse;
    out[(size_t)r * 4 + 1] = acc1 - lse;
    out[(size_t)r * 4 + 2] = acc2 - lse;
    out[(size_t)r * 4 + 3] = acc3 - lse;
}

// ---------------------------------------------------------------------------

extern "C" void kernel_launch(void* const* d_in, const int* in_sizes, int n_in,
                              void* d_out, int out_size) {
    const float* x       = (const float*)d_in[0];   // [N,256]
    const int*   ei_td   = (const int*)d_in[1];     // [2,E]
    const int*   ei_bu   = (const int*)d_in[2];     // [2,E]
    const int*   rootidx = (const int*)d_in[3];     // [R]
    const float* w1 = (const float*)d_in[4];
    const float* b1 = (const float*)d_in[5];
    const float* w2 = (const float*)d_in[6];
    const float* b2 = (const float*)d_in[7];
    const float* w3 = (const float*)d_in[8];
    const float* b3 = (const float*)d_in[9];
    const float* w4 = (const float*)d_in[10];
    const float* b4 = (const float*)d_in[11];
    const float* fcw = (const float*)d_in[12];
    const float* fcb = (const float*)d_in[13];
    float* out = (float*)d_out;

    const int N = in_sizes[0] / 256;
    const int E = in_sizes[1] / 2;
    const int R = in_sizes[3];

    const int* src_td = ei_td;
    const int* dst_td = ei_td + E;
    const int* src_bu = ei_bu;
    const int* dst_bu = ei_bu + E;

    uint32_t *A_td, *B_td, *A_bu, *B_bu, *xh, *wh;
    float *dinv_td, *dinv_bu, *roots_td, *roots_bu;
    int *cnt_td, *cnt_bu, *srcs_td, *srcs_bu;
    cudaGetSymbolAddress((void**)&A_td, g_A_td);
    cudaGetSymbolAddress((void**)&B_td, g_B_td);
    cudaGetSymbolAddress((void**)&A_bu, g_A_bu);
    cudaGetSymbolAddress((void**)&B_bu, g_B_bu);
    cudaGetSymbolAddress((void**)&xh, g_xh);
    cudaGetSymbolAddress((void**)&wh, g_wh);
    cudaGetSymbolAddress((void**)&cnt_td, g_cnt_td);
    cudaGetSymbolAddress((void**)&cnt_bu, g_cnt_bu);
    cudaGetSymbolAddress((void**)&dinv_td, g_dinv_td);
    cudaGetSymbolAddress((void**)&dinv_bu, g_dinv_bu);
    cudaGetSymbolAddress((void**)&srcs_td, g_srcs_td);
    cudaGetSymbolAddress((void**)&srcs_bu, g_srcs_bu);
    cudaGetSymbolAddress((void**)&roots_td, g_roots_td);
    cudaGetSymbolAddress((void**)&roots_bu, g_roots_bu);

    const uint32_t* w1h = wh;                 // 128 pair-rows (K=256)
    const uint32_t* w2h = wh + 128 * 128;     // 64 pair-rows  (K=128)
    const uint32_t* w3h = wh + 192 * 128;     // 128 pair-rows
    const uint32_t* w4h = wh + 320 * 128;     // 64 pair-rows

    // --- conversions + bucketed CSR + dinv ---
    convert_x_kernel<<<ceil_div(N * 64, 256), 256>>>(x, xh, N * 64);
    pack_w_kernel<<<192, 256>>>(w1, w2, w3, w4, wh);
    zero_cnt_kernel<<<ceil_div(N, 256), 256>>>(cnt_td, cnt_bu, N);
    fill_kernel<<<ceil_div(E, 256), 256>>>(src_td, dst_td, src_bu, dst_bu,
                                           cnt_td, cnt_bu, srcs_td, srcs_bu, E);
    dinv_kernel<<<ceil_div(N, 256), 256>>>(cnt_td, cnt_bu, dinv_td, dinv_bu, N);

    const dim3 gemm_grid(ceil_div(N, 128), 2);
    const dim3 agg_grid(ceil_div(N, 8), 2);
    const int r_chunks = R * 32;

    // layer 1 (both branches)
    gemm_tc<256><<<gemm_grid, 256>>>(xh, xh, w1h, w3h, A_td, A_bu, N);
    agg_dual<<<agg_grid, 256>>>(A_td, A_bu, B_td, B_bu, cnt_td, cnt_bu,
                                srcs_td, srcs_bu, dinv_td, dinv_bu, b1, b3, N);
    // layer 2 (both branches)
    gemm_tc<128><<<gemm_grid, 256>>>(B_td, B_bu, w2h, w4h, A_td, A_bu, N);
    agg_dual<<<agg_grid, 256>>>(A_td, A_bu, B_td, B_bu, cnt_td, cnt_bu,
                                srcs_td, srcs_bu, dinv_td, dinv_bu, b2, b4, N);

    gather_roots_kernel<<<ceil_div(r_chunks, 256), 256>>>(B_td, rootidx, roots_td, r_chunks);
    gather_roots_kernel<<<ceil_div(r_chunks, 256), 256>>>(B_bu, rootidx, roots_bu, r_chunks);

    head_kernel<<<ceil_div(R, 128), 128>>>(roots_td, roots_bu, fcw, fcb, out, R);
}

// round 6
// speedup vs baseline: 3.7613x; 1.1557x over previous
#include <cuda_runtime.h>
#include <cuda_fp16.h>
#include <math.h>
#include <stdint.h>

// ---------------------------------------------------------------------------
// GCN_27797028339919 — round 6
//  * A' = dinv .* (XW) computed in GEMM epilogue -> agg is pure gather+add
//  * fill split per branch (grid.y), zero fused into convert
//  * fused root-gather + fc + log_softmax head (warp per root)
// ---------------------------------------------------------------------------

#define MAX_N 100000
#define MAX_R 2048
#define SLOTS 64

__device__ uint32_t g_A_td[(size_t)MAX_N * 64];
__device__ uint32_t g_B_td[(size_t)MAX_N * 64];
__device__ uint32_t g_A_bu[(size_t)MAX_N * 64];
__device__ uint32_t g_B_bu[(size_t)MAX_N * 64];
__device__ uint32_t g_xh[(size_t)MAX_N * 128];       // x as half2 u32
__device__ uint32_t g_wh[(size_t)384 * 128];         // packed weights
__device__ int   g_cnt_td[MAX_N];
__device__ int   g_cnt_bu[MAX_N];
__device__ float g_dinv_td[MAX_N];
__device__ float g_dinv_bu[MAX_N];
__device__ int   g_srcs_td[(size_t)MAX_N * SLOTS];
__device__ int   g_srcs_bu[(size_t)MAX_N * SLOTS];

static inline int ceil_div(int a, int b) { return (a + b - 1) / b; }

// ---------------- bit-cast helpers ----------------

__device__ __forceinline__ uint32_t h2_u32(__half2 h) {
    return *reinterpret_cast<uint32_t*>(&h);
}
__device__ __forceinline__ __half2 u32_h2(uint32_t u) {
    return *reinterpret_cast<__half2*>(&u);
}
__device__ __forceinline__ float4 h4_to_f4(uint2 v) {
    float2 lo = __half22float2(u32_h2(v.x));
    float2 hi = __half22float2(u32_h2(v.y));
    return make_float4(lo.x, lo.y, hi.x, hi.y);
}

// ---------------- prep: convert x + zero counters ----------------

__global__ void prep_kernel(const float* __restrict__ x, uint32_t* __restrict__ xh,
                            int* ca, int* cb, int n4, int N) {
    int i = blockIdx.x * blockDim.x + threadIdx.x;
    if (i < n4) {
        float4 v = *(const float4*)&x[(size_t)i * 4];
        uint2 o;
        o.x = h2_u32(__floats2half2_rn(v.x, v.y));
        o.y = h2_u32(__floats2half2_rn(v.z, v.w));
        *(uint2*)&xh[(size_t)i * 2] = o;
    }
    if (i < N) { ca[i] = 0; cb[i] = 0; }
}

__global__ void pack_w_kernel(const float* __restrict__ w1, const float* __restrict__ w2,
                              const float* __restrict__ w3, const float* __restrict__ w4,
                              uint32_t* __restrict__ wh) {
    int i = blockIdx.x * blockDim.x + threadIdx.x;
    if (i >= 384 * 128) return;
    int prow = i >> 7;
    int n = i & 127;
    const float* w; int p;
    if (prow < 128)      { w = w1; p = prow; }
    else if (prow < 192) { w = w2; p = prow - 128; }
    else if (prow < 320) { w = w3; p = prow - 192; }
    else                 { w = w4; p = prow - 320; }
    float a = w[(size_t)(2 * p) * 128 + n];
    float b = w[(size_t)(2 * p + 1) * 128 + n];
    wh[i] = h2_u32(__floats2half2_rn(a, b));
}

// ---------------- bucket build (per-branch via blockIdx.y) ----------------

__global__ void fill_kernel(const int* __restrict__ src0, const int* __restrict__ dst0,
                            const int* __restrict__ src1, const int* __restrict__ dst1,
                            int* cnt0, int* cnt1,
                            int* __restrict__ srcs0, int* __restrict__ srcs1, int E) {
    int e = blockIdx.x * blockDim.x + threadIdx.x;
    if (e >= E) return;
    const int* src; const int* dst; int* cnt; int* srcs;
    if (blockIdx.y) { src = src1; dst = dst1; cnt = cnt1; srcs = srcs1; }
    else            { src = src0; dst = dst0; cnt = cnt0; srcs = srcs0; }
    int d = __ldg(&dst[e]);
    int p = atomicAdd(&cnt[d], 1);
    if (p < SLOTS) srcs[(size_t)d * SLOTS + p] = __ldg(&src[e]);
}

__global__ void dinv_kernel(const int* ca, const int* cb, float* da, float* db, int n) {
    int i = blockIdx.x * blockDim.x + threadIdx.x;
    if (i < n) {
        da[i] = rsqrtf((float)ca[i] + 1.0f);   // +1 self loop
        db[i] = rsqrtf((float)cb[i] + 1.0f);
    }
}

// ---------------- fp16 mma helpers ----------------

__device__ __forceinline__ void mma_f16(float* c, const uint32_t* a, const uint32_t* b) {
    asm volatile(
        "mma.sync.aligned.m16n8k16.row.col.f32.f16.f16.f32 "
        "{%0,%1,%2,%3}, {%4,%5,%6,%7}, {%8,%9}, {%0,%1,%2,%3};"
        : "+f"(c[0]), "+f"(c[1]), "+f"(c[2]), "+f"(c[3])
        : "r"(a[0]), "r"(a[1]), "r"(a[2]), "r"(a[3]),
          "r"(b[0]), "r"(b[1]));
}

__device__ __forceinline__ int sw_idx(int k, int m) {
    return k * 136 + (m ^ (((k >> 2) & 3) << 3));
}

// ---------------- GEMM: Y[M,128] = dinv .* (X[M,K] @ W[K,128]) --------------

template <int K>
__global__ __launch_bounds__(256, 2)
void gemm_tc(const uint32_t* __restrict__ X0, const uint32_t* __restrict__ X1,
             const uint32_t* __restrict__ W0, const uint32_t* __restrict__ W1,
             uint32_t* __restrict__ Y0, uint32_t* __restrict__ Y1,
             const float* __restrict__ D0, const float* __restrict__ D1, int M) {
    const uint32_t* X = blockIdx.y ? X1 : X0;
    const uint32_t* W = blockIdx.y ? W1 : W0;
    uint32_t*       Y = blockIdx.y ? Y1 : Y0;
    const float*    D = blockIdx.y ? D1 : D0;

    constexpr int K2 = K / 2;
    constexpr int NC = K / 32;

    __shared__ uint32_t xs[2][16 * 136];
    __shared__ uint32_t ws[2][16 * 136];

    const int tid  = threadIdx.x;
    const int lane = tid & 31;
    const int wid  = tid >> 5;
    const int g    = lane >> 2;
    const int tig  = lane & 3;
    const int mbase = (wid & 1) * 64;
    const int nbase = (wid >> 1) * 32;
    const int row0  = blockIdx.x * 128;

    const int xr  = tid >> 2;
    const int xkq = (tid & 3) * 4;
    const int wkr = tid >> 5;
    const int wcq = (tid & 31) * 4;

    float c[4][4][4];
#pragma unroll
    for (int mf = 0; mf < 4; mf++)
#pragma unroll
        for (int nf = 0; nf < 4; nf++)
#pragma unroll
            for (int q = 0; q < 4; q++) c[mf][nf][q] = 0.f;

    uint4 xv[2], wv[2];

    auto loadg = [&](int t) {
        const int p0 = t * 16;
#pragma unroll
        for (int l = 0; l < 2; l++) {
            int r = xr + l * 64;
            int grow = row0 + r;
            xv[l] = (grow < M) ? *(const uint4*)&X[(size_t)grow * K2 + p0 + xkq]
                               : make_uint4(0u, 0u, 0u, 0u);
            wv[l] = *(const uint4*)&W[(size_t)(p0 + wkr + l * 8) * 128 + wcq];
        }
    };
    auto store_s = [&](int buf) {
#pragma unroll
        for (int l = 0; l < 2; l++) {
            int r = xr + l * 64;
            xs[buf][sw_idx(xkq + 0, r)] = xv[l].x;
            xs[buf][sw_idx(xkq + 1, r)] = xv[l].y;
            xs[buf][sw_idx(xkq + 2, r)] = xv[l].z;
            xs[buf][sw_idx(xkq + 3, r)] = xv[l].w;
            *(uint4*)&ws[buf][sw_idx(wkr + l * 8, wcq)] = wv[l];
        }
    };
    auto compute = [&](int buf) {
#pragma unroll
        for (int ks = 0; ks < 2; ks++) {
            const int klo = ks * 8 + tig;
            const int khi = klo + 4;
            uint32_t a[4][4], b[4][2];
#pragma unroll
            for (int mf = 0; mf < 4; mf++) {
                int m0 = mbase + mf * 16 + g;
                a[mf][0] = xs[buf][sw_idx(klo, m0)];
                a[mf][1] = xs[buf][sw_idx(klo, m0 + 8)];
                a[mf][2] = xs[buf][sw_idx(khi, m0)];
                a[mf][3] = xs[buf][sw_idx(khi, m0 + 8)];
            }
#pragma unroll
            for (int nf = 0; nf < 4; nf++) {
                int n0 = nbase + nf * 8 + g;
                b[nf][0] = ws[buf][sw_idx(klo, n0)];
                b[nf][1] = ws[buf][sw_idx(khi, n0)];
            }
#pragma unroll
            for (int mf = 0; mf < 4; mf++)
#pragma unroll
                for (int nf = 0; nf < 4; nf++)
                    mma_f16(c[mf][nf], a[mf], b[nf]);
        }
    };

    loadg(0);
    store_s(0);
    __syncthreads();

    for (int t = 0; t < NC; t++) {
        if (t + 1 < NC) loadg(t + 1);
        compute(t & 1);
        if (t + 1 < NC) {
            store_s((t + 1) & 1);
            __syncthreads();
        }
    }

    // epilogue: scale by dinv[row], store half2 pairs
#pragma unroll
    for (int mf = 0; mf < 4; mf++) {
        int r0 = row0 + mbase + mf * 16 + g;
        float dlo = (r0 < M)     ? __ldg(&D[r0])     : 0.f;
        float dhi = (r0 + 8 < M) ? __ldg(&D[r0 + 8]) : 0.f;
#pragma unroll
        for (int nf = 0; nf < 4; nf++) {
            int np = (nbase + nf * 8 + tig * 2) >> 1;
            if (r0 < M)
                Y[(size_t)r0 * 64 + np] =
                    h2_u32(__floats2half2_rn(dlo * c[mf][nf][0], dlo * c[mf][nf][1]));
            if (r0 + 8 < M)
                Y[(size_t)(r0 + 8) * 64 + np] =
                    h2_u32(__floats2half2_rn(dhi * c[mf][nf][2], dhi * c[mf][nf][3]));
        }
    }
}

// ---------------- aggregation: B = elu(bias + dinv[d]*(sum A'[s] + A'[d])) --

__device__ __forceinline__ float elu1(float x) {
    return x > 0.f ? x : expm1f(x);
}

__global__ __launch_bounds__(256)
void agg_dual(const uint32_t* __restrict__ A0, const uint32_t* __restrict__ A1,
              uint32_t* __restrict__ B0, uint32_t* __restrict__ B1,
              const int* __restrict__ cnt0, const int* __restrict__ cnt1,
              const int* __restrict__ srcs0, const int* __restrict__ srcs1,
              const float* __restrict__ dinv0, const float* __restrict__ dinv1,
              const float* __restrict__ bias0, const float* __restrict__ bias1,
              int N) {
    int node = (blockIdx.x * 256 + threadIdx.x) >> 5;
    if (node >= N) return;
    int lane = threadIdx.x & 31;

    const uint32_t* A;  uint32_t* B;  const int* cnt;  const int* srcs;
    const float* dinv;  const float* bias;
    if (blockIdx.y) { A = A1; B = B1; cnt = cnt1; srcs = srcs1; dinv = dinv1; bias = bias1; }
    else            { A = A0; B = B0; cnt = cnt0; srcs = srcs0; dinv = dinv0; bias = bias0; }

    const uint2* A2 = (const uint2*)A;

    // self loop: A'[node]
    float4 acc = h4_to_f4(A2[(size_t)node * 32 + lane]);

    int c = min(__ldg(&cnt[node]), SLOTS);
    const int* sp = &srcs[(size_t)node * SLOTS];

    int i = 0;
    for (; i + 4 <= c; i += 4) {
        int4 s4 = *(const int4*)&sp[i];
        float4 v0 = h4_to_f4(__ldg(&A2[(size_t)s4.x * 32 + lane]));
        float4 v1 = h4_to_f4(__ldg(&A2[(size_t)s4.y * 32 + lane]));
        float4 v2 = h4_to_f4(__ldg(&A2[(size_t)s4.z * 32 + lane]));
        float4 v3 = h4_to_f4(__ldg(&A2[(size_t)s4.w * 32 + lane]));
        acc.x += v0.x + v1.x + v2.x + v3.x;
        acc.y += v0.y + v1.y + v2.y + v3.y;
        acc.z += v0.z + v1.z + v2.z + v3.z;
        acc.w += v0.w + v1.w + v2.w + v3.w;
    }
    for (; i < c; i++) {
        int s = __ldg(&sp[i]);
        float4 v = h4_to_f4(__ldg(&A2[(size_t)s * 32 + lane]));
        acc.x += v.x; acc.y += v.y; acc.z += v.z; acc.w += v.w;
    }

    const float dd = __ldg(&dinv[node]);
    float4 bv = *(const float4*)&bias[lane * 4];
    acc.x = elu1(fmaf(dd, acc.x, bv.x));
    acc.y = elu1(fmaf(dd, acc.y, bv.y));
    acc.z = elu1(fmaf(dd, acc.z, bv.z));
    acc.w = elu1(fmaf(dd, acc.w, bv.w));

    uint2 o;
    o.x = h2_u32(__floats2half2_rn(acc.x, acc.y));
    o.y = h2_u32(__floats2half2_rn(acc.z, acc.w));
    ((uint2*)B)[(size_t)node * 32 + lane] = o;
}

// ---------------- fused head: gather roots + fc + log_softmax ---------------
// warp per root; lane l owns features 4l..4l+3 of each branch.

__global__ __launch_bounds__(256)
void head_kernel(const uint32_t* __restrict__ Btd, const uint32_t* __restrict__ Bbu,
                 const int* __restrict__ roots,
                 const float* __restrict__ fcw,   // [256,4]
                 const float* __restrict__ fcb,   // [4]
                 float* __restrict__ out, int R) {
    int r = blockIdx.x * 8 + (threadIdx.x >> 5);
    if (r >= R) return;
    int lane = threadIdx.x & 31;
    int node = __ldg(&roots[r]);

    float4 ftd = h4_to_f4(((const uint2*)Btd)[(size_t)node * 32 + lane]);
    float4 fbu = h4_to_f4(((const uint2*)Bbu)[(size_t)node * 32 + lane]);

    float s0 = 0.f, s1 = 0.f, s2 = 0.f, s3 = 0.f;
    const float* ft = &ftd.x;
    const float* fb = &fbu.x;
#pragma unroll
    for (int j = 0; j < 4; j++) {
        int k = lane * 4 + j;
        float4 wt = *(const float4*)&fcw[(size_t)k * 4];
        float4 wb = *(const float4*)&fcw[(size_t)(128 + k) * 4];
        s0 = fmaf(ft[j], wt.x, fmaf(fb[j], wb.x, s0));
        s1 = fmaf(ft[j], wt.y, fmaf(fb[j], wb.y, s1));
        s2 = fmaf(ft[j], wt.z, fmaf(fb[j], wb.z, s2));
        s3 = fmaf(ft[j], wt.w, fmaf(fb[j], wb.w, s3));
    }
#pragma unroll
    for (int off = 16; off; off >>= 1) {
        s0 += __shfl_xor_sync(0xffffffffu, s0, off);
        s1 += __shfl_xor_sync(0xffffffffu, s1, off);
        s2 += __shfl_xor_sync(0xffffffffu, s2, off);
        s3 += __shfl_xor_sync(0xffffffffu, s3, off);
    }
    if (lane == 0) {
        s0 += fcb[0]; s1 += fcb[1]; s2 += fcb[2]; s3 += fcb[3];
        float m = fmaxf(fmaxf(s0, s1), fmaxf(s2, s3));
        float s = expf(s0 - m) + expf(s1 - m) + expf(s2 - m) + expf(s3 - m);
        float lse = m + logf(s);
        float4 o = make_float4(s0 - lse, s1 - lse, s2 - lse, s3 - lse);
        *(float4*)&out[(size_t)r * 4] = o;
    }
}

// ---------------------------------------------------------------------------

extern "C" void kernel_launch(void* const* d_in, const int* in_sizes, int n_in,
                              void* d_out, int out_size) {
    const float* x       = (const float*)d_in[0];
    const int*   ei_td   = (const int*)d_in[1];
    const int*   ei_bu   = (const int*)d_in[2];
    const int*   rootidx = (const int*)d_in[3];
    const float* w1 = (const float*)d_in[4];
    const float* b1 = (const float*)d_in[5];
    const float* w2 = (const float*)d_in[6];
    const float* b2 = (const float*)d_in[7];
    const float* w3 = (const float*)d_in[8];
    const float* b3 = (const float*)d_in[9];
    const float* w4 = (const float*)d_in[10];
    const float* b4 = (const float*)d_in[11];
    const float* fcw = (const float*)d_in[12];
    const float* fcb = (const float*)d_in[13];
    float* out = (float*)d_out;

    const int N = in_sizes[0] / 256;
    const int E = in_sizes[1] / 2;
    const int R = in_sizes[3];

    const int* src_td = ei_td;
    const int* dst_td = ei_td + E;
    const int* src_bu = ei_bu;
    const int* dst_bu = ei_bu + E;

    uint32_t *A_td, *B_td, *A_bu, *B_bu, *xh, *wh;
    float *dinv_td, *dinv_bu;
    int *cnt_td, *cnt_bu, *srcs_td, *srcs_bu;
    cudaGetSymbolAddress((void**)&A_td, g_A_td);
    cudaGetSymbolAddress((void**)&B_td, g_B_td);
    cudaGetSymbolAddress((void**)&A_bu, g_A_bu);
    cudaGetSymbolAddress((void**)&B_bu, g_B_bu);
    cudaGetSymbolAddress((void**)&xh, g_xh);
    cudaGetSymbolAddress((void**)&wh, g_wh);
    cudaGetSymbolAddress((void**)&cnt_td, g_cnt_td);
    cudaGetSymbolAddress((void**)&cnt_bu, g_cnt_bu);
    cudaGetSymbolAddress((void**)&dinv_td, g_dinv_td);
    cudaGetSymbolAddress((void**)&dinv_bu, g_dinv_bu);
    cudaGetSymbolAddress((void**)&srcs_td, g_srcs_td);
    cudaGetSymbolAddress((void**)&srcs_bu, g_srcs_bu);

    const uint32_t* w1h = wh;
    const uint32_t* w2h = wh + 128 * 128;
    const uint32_t* w3h = wh + 192 * 128;
    const uint32_t* w4h = wh + 320 * 128;

    // --- prep: convert x + zero counters, pack weights, fill buckets, dinv --
    prep_kernel<<<ceil_div(N * 64, 256), 256>>>(x, xh, cnt_td, cnt_bu, N * 64, N);
    pack_w_kernel<<<192, 256>>>(w1, w2, w3, w4, wh);
    fill_kernel<<<dim3(ceil_div(E, 256), 2), 256>>>(src_td, dst_td, src_bu, dst_bu,
                                                    cnt_td, cnt_bu, srcs_td, srcs_bu, E);
    dinv_kernel<<<ceil_div(N, 256), 256>>>(cnt_td, cnt_bu, dinv_td, dinv_bu, N);

    const dim3 gemm_grid(ceil_div(N, 128), 2);
    const dim3 agg_grid(ceil_div(N, 8), 2);

    // layer 1
    gemm_tc<256><<<gemm_grid, 256>>>(xh, xh, w1h, w3h, A_td, A_bu, dinv_td, dinv_bu, N);
    agg_dual<<<agg_grid, 256>>>(A_td, A_bu, B_td, B_bu, cnt_td, cnt_bu,
                                srcs_td, srcs_bu, dinv_td, dinv_bu, b1, b3, N);
    // layer 2
    gemm_tc<128><<<gemm_grid, 256>>>(B_td, B_bu, w2h, w4h, A_td, A_bu, dinv_td, dinv_bu, N);
    agg_dual<<<agg_grid, 256>>>(A_td, A_bu, B_td, B_bu, cnt_td, cnt_bu,
                                srcs_td, srcs_bu, dinv_td, dinv_bu, b2, b4, N);

    // fused head
    head_kernel<<<ceil_div(R, 8), 256>>>(B_td, B_bu, rootidx, fcw, fcb, out, R);
}

// round 7
// speedup vs baseline: 3.9490x; 1.0499x over previous
#include <cuda_runtime.h>
#include <cuda_fp16.h>
#include <math.h>
#include <stdint.h>

// ---------------------------------------------------------------------------
// GCN_27797028339919 — round 7
//  * multi-stream graph-captured pipeline: prep fork + independent td/bu
//    branch chains (tensor-bound GEMM overlaps L2-bound aggregation)
//  * A' = dinv .* (XW) in GEMM epilogue; agg = pure gather+add (+bias,ELU)
// ---------------------------------------------------------------------------

#define MAX_N 100000
#define MAX_R 2048
#define SLOTS 64

__device__ uint32_t g_A_td[(size_t)MAX_N * 64];
__device__ uint32_t g_B_td[(size_t)MAX_N * 64];
__device__ uint32_t g_A_bu[(size_t)MAX_N * 64];
__device__ uint32_t g_B_bu[(size_t)MAX_N * 64];
__device__ uint32_t g_xh[(size_t)MAX_N * 128];
__device__ uint32_t g_wh[(size_t)384 * 128];
__device__ int   g_cnt_td[MAX_N];
__device__ int   g_cnt_bu[MAX_N];
__device__ float g_dinv_td[MAX_N];
__device__ float g_dinv_bu[MAX_N];
__device__ int   g_srcs_td[(size_t)MAX_N * SLOTS];
__device__ int   g_srcs_bu[(size_t)MAX_N * SLOTS];

static inline int ceil_div(int a, int b) { return (a + b - 1) / b; }

// ---------------- bit-cast helpers ----------------

__device__ __forceinline__ uint32_t h2_u32(__half2 h) {
    return *reinterpret_cast<uint32_t*>(&h);
}
__device__ __forceinline__ __half2 u32_h2(uint32_t u) {
    return *reinterpret_cast<__half2*>(&u);
}
__device__ __forceinline__ float4 h4_to_f4(uint2 v) {
    float2 lo = __half22float2(u32_h2(v.x));
    float2 hi = __half22float2(u32_h2(v.y));
    return make_float4(lo.x, lo.y, hi.x, hi.y);
}

// ---------------- prep kernels ----------------

__global__ void convert_x_kernel(const float* __restrict__ x,
                                 uint32_t* __restrict__ xh, int n4) {
    int i = blockIdx.x * blockDim.x + threadIdx.x;
    if (i >= n4) return;
    float4 v = *(const float4*)&x[(size_t)i * 4];
    uint2 o;
    o.x = h2_u32(__floats2half2_rn(v.x, v.y));
    o.y = h2_u32(__floats2half2_rn(v.z, v.w));
    *(uint2*)&xh[(size_t)i * 2] = o;
}

__global__ void pack_w_kernel(const float* __restrict__ w1, const float* __restrict__ w2,
                              const float* __restrict__ w3, const float* __restrict__ w4,
                              uint32_t* __restrict__ wh) {
    int i = blockIdx.x * blockDim.x + threadIdx.x;
    if (i >= 384 * 128) return;
    int prow = i >> 7;
    int n = i & 127;
    const float* w; int p;
    if (prow < 128)      { w = w1; p = prow; }
    else if (prow < 192) { w = w2; p = prow - 128; }
    else if (prow < 320) { w = w3; p = prow - 192; }
    else                 { w = w4; p = prow - 320; }
    float a = w[(size_t)(2 * p) * 128 + n];
    float b = w[(size_t)(2 * p + 1) * 128 + n];
    wh[i] = h2_u32(__floats2half2_rn(a, b));
}

__global__ void zero_cnt_kernel(int* a, int* b, int n) {
    int i = blockIdx.x * blockDim.x + threadIdx.x;
    if (i < n) { a[i] = 0; b[i] = 0; }
}

__global__ void fill_kernel(const int* __restrict__ src0, const int* __restrict__ dst0,
                            const int* __restrict__ src1, const int* __restrict__ dst1,
                            int* cnt0, int* cnt1,
                            int* __restrict__ srcs0, int* __restrict__ srcs1, int E) {
    int e = blockIdx.x * blockDim.x + threadIdx.x;
    if (e >= E) return;
    const int* src; const int* dst; int* cnt; int* srcs;
    if (blockIdx.y) { src = src1; dst = dst1; cnt = cnt1; srcs = srcs1; }
    else            { src = src0; dst = dst0; cnt = cnt0; srcs = srcs0; }
    int d = __ldg(&dst[e]);
    int p = atomicAdd(&cnt[d], 1);
    if (p < SLOTS) srcs[(size_t)d * SLOTS + p] = __ldg(&src[e]);
}

__global__ void dinv_kernel(const int* ca, const int* cb, float* da, float* db, int n) {
    int i = blockIdx.x * blockDim.x + threadIdx.x;
    if (i < n) {
        da[i] = rsqrtf((float)ca[i] + 1.0f);
        db[i] = rsqrtf((float)cb[i] + 1.0f);
    }
}

// ---------------- fp16 mma helpers ----------------

__device__ __forceinline__ void mma_f16(float* c, const uint32_t* a, const uint32_t* b) {
    asm volatile(
        "mma.sync.aligned.m16n8k16.row.col.f32.f16.f16.f32 "
        "{%0,%1,%2,%3}, {%4,%5,%6,%7}, {%8,%9}, {%0,%1,%2,%3};"
        : "+f"(c[0]), "+f"(c[1]), "+f"(c[2]), "+f"(c[3])
        : "r"(a[0]), "r"(a[1]), "r"(a[2]), "r"(a[3]),
          "r"(b[0]), "r"(b[1]));
}

__device__ __forceinline__ int sw_idx(int k, int m) {
    return k * 136 + (m ^ (((k >> 2) & 3) << 3));
}

// ---------------- GEMM (per branch): Y = dinv .* (X @ W) ----------------

template <int K>
__global__ __launch_bounds__(256, 2)
void gemm_tc(const uint32_t* __restrict__ X, const uint32_t* __restrict__ W,
             uint32_t* __restrict__ Y, const float* __restrict__ D, int M) {
    constexpr int K2 = K / 2;
    constexpr int NC = K / 32;

    __shared__ uint32_t xs[2][16 * 136];
    __shared__ uint32_t ws[2][16 * 136];

    const int tid  = threadIdx.x;
    const int lane = tid & 31;
    const int wid  = tid >> 5;
    const int g    = lane >> 2;
    const int tig  = lane & 3;
    const int mbase = (wid & 1) * 64;
    const int nbase = (wid >> 1) * 32;
    const int row0  = blockIdx.x * 128;

    const int xr  = tid >> 2;
    const int xkq = (tid & 3) * 4;
    const int wkr = tid >> 5;
    const int wcq = (tid & 31) * 4;

    float c[4][4][4];
#pragma unroll
    for (int mf = 0; mf < 4; mf++)
#pragma unroll
        for (int nf = 0; nf < 4; nf++)
#pragma unroll
            for (int q = 0; q < 4; q++) c[mf][nf][q] = 0.f;

    uint4 xv[2], wv[2];

    auto loadg = [&](int t) {
        const int p0 = t * 16;
#pragma unroll
        for (int l = 0; l < 2; l++) {
            int r = xr + l * 64;
            int grow = row0 + r;
            xv[l] = (grow < M) ? *(const uint4*)&X[(size_t)grow * K2 + p0 + xkq]
                               : make_uint4(0u, 0u, 0u, 0u);
            wv[l] = *(const uint4*)&W[(size_t)(p0 + wkr + l * 8) * 128 + wcq];
        }
    };
    auto store_s = [&](int buf) {
#pragma unroll
        for (int l = 0; l < 2; l++) {
            int r = xr + l * 64;
            xs[buf][sw_idx(xkq + 0, r)] = xv[l].x;
            xs[buf][sw_idx(xkq + 1, r)] = xv[l].y;
            xs[buf][sw_idx(xkq + 2, r)] = xv[l].z;
            xs[buf][sw_idx(xkq + 3, r)] = xv[l].w;
            *(uint4*)&ws[buf][sw_idx(wkr + l * 8, wcq)] = wv[l];
        }
    };
    auto compute = [&](int buf) {
#pragma unroll
        for (int ks = 0; ks < 2; ks++) {
            const int klo = ks * 8 + tig;
            const int khi = klo + 4;
            uint32_t a[4][4], b[4][2];
#pragma unroll
            for (int mf = 0; mf < 4; mf++) {
                int m0 = mbase + mf * 16 + g;
                a[mf][0] = xs[buf][sw_idx(klo, m0)];
                a[mf][1] = xs[buf][sw_idx(klo, m0 + 8)];
                a[mf][2] = xs[buf][sw_idx(khi, m0)];
                a[mf][3] = xs[buf][sw_idx(khi, m0 + 8)];
            }
#pragma unroll
            for (int nf = 0; nf < 4; nf++) {
                int n0 = nbase + nf * 8 + g;
                b[nf][0] = ws[buf][sw_idx(klo, n0)];
                b[nf][1] = ws[buf][sw_idx(khi, n0)];
            }
#pragma unroll
            for (int mf = 0; mf < 4; mf++)
#pragma unroll
                for (int nf = 0; nf < 4; nf++)
                    mma_f16(c[mf][nf], a[mf], b[nf]);
        }
    };

    loadg(0);
    store_s(0);
    __syncthreads();

    for (int t = 0; t < NC; t++) {
        if (t + 1 < NC) loadg(t + 1);
        compute(t & 1);
        if (t + 1 < NC) {
            store_s((t + 1) & 1);
            __syncthreads();
        }
    }

#pragma unroll
    for (int mf = 0; mf < 4; mf++) {
        int r0 = row0 + mbase + mf * 16 + g;
        float dlo = (r0 < M)     ? __ldg(&D[r0])     : 0.f;
        float dhi = (r0 + 8 < M) ? __ldg(&D[r0 + 8]) : 0.f;
#pragma unroll
        for (int nf = 0; nf < 4; nf++) {
            int np = (nbase + nf * 8 + tig * 2) >> 1;
            if (r0 < M)
                Y[(size_t)r0 * 64 + np] =
                    h2_u32(__floats2half2_rn(dlo * c[mf][nf][0], dlo * c[mf][nf][1]));
            if (r0 + 8 < M)
                Y[(size_t)(r0 + 8) * 64 + np] =
                    h2_u32(__floats2half2_rn(dhi * c[mf][nf][2], dhi * c[mf][nf][3]));
        }
    }
}

// ---------------- aggregation (per branch) ----------------

__device__ __forceinline__ float elu1(float x) {
    return x > 0.f ? x : expm1f(x);
}

__global__ __launch_bounds__(256)
void agg_one(const uint32_t* __restrict__ A, uint32_t* __restrict__ B,
             const int* __restrict__ cnt, const int* __restrict__ srcs,
             const float* __restrict__ dinv, const float* __restrict__ bias,
             int N) {
    int node = (blockIdx.x * 256 + threadIdx.x) >> 5;
    if (node >= N) return;
    int lane = threadIdx.x & 31;

    const uint2* A2 = (const uint2*)A;
    float4 acc = h4_to_f4(A2[(size_t)node * 32 + lane]);   // self loop

    int c = min(__ldg(&cnt[node]), SLOTS);
    const int* sp = &srcs[(size_t)node * SLOTS];

    int i = 0;
    for (; i + 4 <= c; i += 4) {
        int4 s4 = *(const int4*)&sp[i];
        float4 v0 = h4_to_f4(__ldg(&A2[(size_t)s4.x * 32 + lane]));
        float4 v1 = h4_to_f4(__ldg(&A2[(size_t)s4.y * 32 + lane]));
        float4 v2 = h4_to_f4(__ldg(&A2[(size_t)s4.z * 32 + lane]));
        float4 v3 = h4_to_f4(__ldg(&A2[(size_t)s4.w * 32 + lane]));
        acc.x += v0.x + v1.x + v2.x + v3.x;
        acc.y += v0.y + v1.y + v2.y + v3.y;
        acc.z += v0.z + v1.z + v2.z + v3.z;
        acc.w += v0.w + v1.w + v2.w + v3.w;
    }
    for (; i < c; i++) {
        int s = __ldg(&sp[i]);
        float4 v = h4_to_f4(__ldg(&A2[(size_t)s * 32 + lane]));
        acc.x += v.x; acc.y += v.y; acc.z += v.z; acc.w += v.w;
    }

    const float dd = __ldg(&dinv[node]);
    float4 bv = *(const float4*)&bias[lane * 4];
    acc.x = elu1(fmaf(dd, acc.x, bv.x));
    acc.y = elu1(fmaf(dd, acc.y, bv.y));
    acc.z = elu1(fmaf(dd, acc.z, bv.z));
    acc.w = elu1(fmaf(dd, acc.w, bv.w));

    uint2 o;
    o.x = h2_u32(__floats2half2_rn(acc.x, acc.y));
    o.y = h2_u32(__floats2half2_rn(acc.z, acc.w));
    ((uint2*)B)[(size_t)node * 32 + lane] = o;
}

// ---------------- fused head ----------------

__global__ __launch_bounds__(256)
void head_kernel(const uint32_t* __restrict__ Btd, const uint32_t* __restrict__ Bbu,
                 const int* __restrict__ roots,
                 const float* __restrict__ fcw, const float* __restrict__ fcb,
                 float* __restrict__ out, int R) {
    int r = blockIdx.x * 8 + (threadIdx.x >> 5);
    if (r >= R) return;
    int lane = threadIdx.x & 31;
    int node = __ldg(&roots[r]);

    float4 ftd = h4_to_f4(((const uint2*)Btd)[(size_t)node * 32 + lane]);
    float4 fbu = h4_to_f4(((const uint2*)Bbu)[(size_t)node * 32 + lane]);

    float s0 = 0.f, s1 = 0.f, s2 = 0.f, s3 = 0.f;
    const float* ft = &ftd.x;
    const float* fb = &fbu.x;
#pragma unroll
    for (int j = 0; j < 4; j++) {
        int k = lane * 4 + j;
        float4 wt = *(const float4*)&fcw[(size_t)k * 4];
        float4 wb = *(const float4*)&fcw[(size_t)(128 + k) * 4];
        s0 = fmaf(ft[j], wt.x, fmaf(fb[j], wb.x, s0));
        s1 = fmaf(ft[j], wt.y, fmaf(fb[j], wb.y, s1));
        s2 = fmaf(ft[j], wt.z, fmaf(fb[j], wb.z, s2));
        s3 = fmaf(ft[j], wt.w, fmaf(fb[j], wb.w, s3));
    }
#pragma unroll
    for (int off = 16; off; off >>= 1) {
        s0 += __shfl_xor_sync(0xffffffffu, s0, off);
        s1 += __shfl_xor_sync(0xffffffffu, s1, off);
        s2 += __shfl_xor_sync(0xffffffffu, s2, off);
        s3 += __shfl_xor_sync(0xffffffffu, s3, off);
    }
    if (lane == 0) {
        s0 += fcb[0]; s1 += fcb[1]; s2 += fcb[2]; s3 += fcb[3];
        float m = fmaxf(fmaxf(s0, s1), fmaxf(s2, s3));
        float s = expf(s0 - m) + expf(s1 - m) + expf(s2 - m) + expf(s3 - m);
        float lse = m + logf(s);
        float4 o = make_float4(s0 - lse, s1 - lse, s2 - lse, s3 - lse);
        *(float4*)&out[(size_t)r * 4] = o;
    }
}

// ---------------------------------------------------------------------------

extern "C" void kernel_launch(void* const* d_in, const int* in_sizes, int n_in,
                              void* d_out, int out_size) {
    const float* x       = (const float*)d_in[0];
    const int*   ei_td   = (const int*)d_in[1];
    const int*   ei_bu   = (const int*)d_in[2];
    const int*   rootidx = (const int*)d_in[3];
    const float* w1 = (const float*)d_in[4];
    const float* b1 = (const float*)d_in[5];
    const float* w2 = (const float*)d_in[6];
    const float* b2 = (const float*)d_in[7];
    const float* w3 = (const float*)d_in[8];
    const float* b3 = (const float*)d_in[9];
    const float* w4 = (const float*)d_in[10];
    const float* b4 = (const float*)d_in[11];
    const float* fcw = (const float*)d_in[12];
    const float* fcb = (const float*)d_in[13];
    float* out = (float*)d_out;

    const int N = in_sizes[0] / 256;
    const int E = in_sizes[1] / 2;
    const int R = in_sizes[3];

    const int* src_td = ei_td;
    const int* dst_td = ei_td + E;
    const int* src_bu = ei_bu;
    const int* dst_bu = ei_bu + E;

    uint32_t *A_td, *B_td, *A_bu, *B_bu, *xh, *wh;
    float *dinv_td, *dinv_bu;
    int *cnt_td, *cnt_bu, *srcs_td, *srcs_bu;
    cudaGetSymbolAddress((void**)&A_td, g_A_td);
    cudaGetSymbolAddress((void**)&B_td, g_B_td);
    cudaGetSymbolAddress((void**)&A_bu, g_A_bu);
    cudaGetSymbolAddress((void**)&B_bu, g_B_bu);
    cudaGetSymbolAddress((void**)&xh, g_xh);
    cudaGetSymbolAddress((void**)&wh, g_wh);
    cudaGetSymbolAddress((void**)&cnt_td, g_cnt_td);
    cudaGetSymbolAddress((void**)&cnt_bu, g_cnt_bu);
    cudaGetSymbolAddress((void**)&dinv_td, g_dinv_td);
    cudaGetSymbolAddress((void**)&dinv_bu, g_dinv_bu);
    cudaGetSymbolAddress((void**)&srcs_td, g_srcs_td);
    cudaGetSymbolAddress((void**)&srcs_bu, g_srcs_bu);

    const uint32_t* w1h = wh;
    const uint32_t* w2h = wh + 128 * 128;
    const uint32_t* w3h = wh + 192 * 128;
    const uint32_t* w4h = wh + 320 * 128;

    // --- streams / events (host-side objects, created once) ---
    static cudaStream_t sB = nullptr, sC = nullptr;
    static cudaEvent_t evFork, evXh, evPrep, evWh, evBuDone;
    if (!sB) {
        cudaStreamCreateWithFlags(&sB, cudaStreamNonBlocking);
        cudaStreamCreateWithFlags(&sC, cudaStreamNonBlocking);
        cudaEventCreateWithFlags(&evFork,  cudaEventDisableTiming);
        cudaEventCreateWithFlags(&evXh,    cudaEventDisableTiming);
        cudaEventCreateWithFlags(&evPrep,  cudaEventDisableTiming);
        cudaEventCreateWithFlags(&evWh,    cudaEventDisableTiming);
        cudaEventCreateWithFlags(&evBuDone,cudaEventDisableTiming);
    }
    cudaStream_t sA = 0;   // capture-origin (default) stream

    const int gemm_blocks = ceil_div(N, 128);
    const int agg_blocks  = ceil_div(N, 8);

    // fork
    cudaEventRecord(evFork, sA);
    cudaStreamWaitEvent(sB, evFork, 0);
    cudaStreamWaitEvent(sC, evFork, 0);

    // sA: convert x -> fp16
    convert_x_kernel<<<ceil_div(N * 64, 256), 256, 0, sA>>>(x, xh, N * 64);
    cudaEventRecord(evXh, sA);

    // sB: zero counters -> fill buckets (both branches) -> dinv
    zero_cnt_kernel<<<ceil_div(N, 256), 256, 0, sB>>>(cnt_td, cnt_bu, N);
    fill_kernel<<<dim3(ceil_div(E, 256), 2), 256, 0, sB>>>(
        src_td, dst_td, src_bu, dst_bu, cnt_td, cnt_bu, srcs_td, srcs_bu, E);
    dinv_kernel<<<ceil_div(N, 256), 256, 0, sB>>>(cnt_td, cnt_bu, dinv_td, dinv_bu, N);
    cudaEventRecord(evPrep, sB);

    // sC: pack weights
    pack_w_kernel<<<192, 256, 0, sC>>>(w1, w2, w3, w4, wh);
    cudaEventRecord(evWh, sC);

    // --- td branch on sA (needs xh[sA], prep[sB], wh[sC]) ---
    cudaStreamWaitEvent(sA, evPrep, 0);
    cudaStreamWaitEvent(sA, evWh, 0);
    gemm_tc<256><<<gemm_blocks, 256, 0, sA>>>(xh, w1h, A_td, dinv_td, N);
    agg_one<<<agg_blocks, 256, 0, sA>>>(A_td, B_td, cnt_td, srcs_td, dinv_td, b1, N);
    gemm_tc<128><<<gemm_blocks, 256, 0, sA>>>(B_td, w2h, A_td, dinv_td, N);
    agg_one<<<agg_blocks, 256, 0, sA>>>(A_td, B_td, cnt_td, srcs_td, dinv_td, b2, N);

    // --- bu branch on sB (needs xh[sA], wh[sC]; prep already on sB) ---
    cudaStreamWaitEvent(sB, evXh, 0);
    cudaStreamWaitEvent(sB, evWh, 0);
    gemm_tc<256><<<gemm_blocks, 256, 0, sB>>>(xh, w3h, A_bu, dinv_bu, N);
    agg_one<<<agg_blocks, 256, 0, sB>>>(A_bu, B_bu, cnt_bu, srcs_bu, dinv_bu, b3, N);
    gemm_tc<128><<<gemm_blocks, 256, 0, sB>>>(B_bu, w4h, A_bu, dinv_bu, N);
    agg_one<<<agg_blocks, 256, 0, sB>>>(A_bu, B_bu, cnt_bu, srcs_bu, dinv_bu, b4, N);
    cudaEventRecord(evBuDone, sB);

    // join + head on sA
    cudaStreamWaitEvent(sA, evBuDone, 0);
    head_kernel<<<ceil_div(R, 8), 256, 0, sA>>>(B_td, B_bu, rootidx, fcw, fcb, out, R);
}

// round 8
// speedup vs baseline: 7.1145x; 1.8016x over previous
#include <cuda_runtime.h>
#include <cuda_fp16.h>
#include <math.h>
#include <stdint.h>

// ---------------------------------------------------------------------------
// GCN_27797028339919 — round 8
//  * layer 2 computed ONLY at roots via linearity:
//      h2[r] = elu(b2 + (dinv[r]*(B1s[r]+sum_bucket B1s[s])) @ W2)
//    where B1s[i] = dinv[i]*elu(layer1) — so layer-2 full GEMM+agg vanish.
//  * layer-1 agg restricted to S = roots ∪ in-neighbors(roots) (mark+compact)
//  * multi-stream graph-captured pipeline as in R7
// ---------------------------------------------------------------------------

#define MAX_N 100000
#define MAX_R 2048
#define SLOTS 64

__device__ uint32_t g_A_td[(size_t)MAX_N * 64];
__device__ uint32_t g_B_td[(size_t)MAX_N * 64];
__device__ uint32_t g_A_bu[(size_t)MAX_N * 64];
__device__ uint32_t g_B_bu[(size_t)MAX_N * 64];
__device__ uint32_t g_xh[(size_t)MAX_N * 128];
__device__ uint32_t g_wh[(size_t)384 * 128];
__device__ int   g_cnt_td[MAX_N];
__device__ int   g_cnt_bu[MAX_N];
__device__ float g_dinv_td[MAX_N];
__device__ float g_dinv_bu[MAX_N];
__device__ int   g_srcs_td[(size_t)MAX_N * SLOTS];
__device__ int   g_srcs_bu[(size_t)MAX_N * SLOTS];
__device__ char  g_mark_td[MAX_N];
__device__ char  g_mark_bu[MAX_N];
__device__ int   g_list_td[MAX_N];
__device__ int   g_list_bu[MAX_N];
__device__ int   g_listcnt[2];
__device__ uint32_t g_g_td[(size_t)MAX_R * 64];   // gathered layer-2 input
__device__ uint32_t g_g_bu[(size_t)MAX_R * 64];
__device__ uint32_t g_r_td[(size_t)MAX_R * 64];   // layer-2 output at roots
__device__ uint32_t g_r_bu[(size_t)MAX_R * 64];

static inline int ceil_div(int a, int b) { return (a + b - 1) / b; }

// ---------------- bit-cast helpers ----------------

__device__ __forceinline__ uint32_t h2_u32(__half2 h) {
    return *reinterpret_cast<uint32_t*>(&h);
}
__device__ __forceinline__ __half2 u32_h2(uint32_t u) {
    return *reinterpret_cast<__half2*>(&u);
}
__device__ __forceinline__ float4 h4_to_f4(uint2 v) {
    float2 lo = __half22float2(u32_h2(v.x));
    float2 hi = __half22float2(u32_h2(v.y));
    return make_float4(lo.x, lo.y, hi.x, hi.y);
}

// ---------------- prep kernels ----------------

__global__ void convert_x_kernel(const float* __restrict__ x,
                                 uint32_t* __restrict__ xh, int n4) {
    int i = blockIdx.x * blockDim.x + threadIdx.x;
    if (i >= n4) return;
    float4 v = *(const float4*)&x[(size_t)i * 4];
    uint2 o;
    o.x = h2_u32(__floats2half2_rn(v.x, v.y));
    o.y = h2_u32(__floats2half2_rn(v.z, v.w));
    *(uint2*)&xh[(size_t)i * 2] = o;
}

__global__ void pack_w_kernel(const float* __restrict__ w1, const float* __restrict__ w2,
                              const float* __restrict__ w3, const float* __restrict__ w4,
                              uint32_t* __restrict__ wh) {
    int i = blockIdx.x * blockDim.x + threadIdx.x;
    if (i >= 384 * 128) return;
    int prow = i >> 7;
    int n = i & 127;
    const float* w; int p;
    if (prow < 128)      { w = w1; p = prow; }
    else if (prow < 192) { w = w2; p = prow - 128; }
    else if (prow < 320) { w = w3; p = prow - 192; }
    else                 { w = w4; p = prow - 320; }
    float a = w[(size_t)(2 * p) * 128 + n];
    float b = w[(size_t)(2 * p + 1) * 128 + n];
    wh[i] = h2_u32(__floats2half2_rn(a, b));
}

__global__ void zero_kernel(int* ca, int* cb, char* ma, char* mb, int* lc, int n) {
    int i = blockIdx.x * blockDim.x + threadIdx.x;
    if (i < n) { ca[i] = 0; cb[i] = 0; ma[i] = 0; mb[i] = 0; }
    if (i < 2) lc[i] = 0;
}

__global__ void fill_kernel(const int* __restrict__ src0, const int* __restrict__ dst0,
                            const int* __restrict__ src1, const int* __restrict__ dst1,
                            int* cnt0, int* cnt1,
                            int* __restrict__ srcs0, int* __restrict__ srcs1, int E) {
    int e = blockIdx.x * blockDim.x + threadIdx.x;
    if (e >= E) return;
    const int* src; const int* dst; int* cnt; int* srcs;
    if (blockIdx.y) { src = src1; dst = dst1; cnt = cnt1; srcs = srcs1; }
    else            { src = src0; dst = dst0; cnt = cnt0; srcs = srcs0; }
    int d = __ldg(&dst[e]);
    int p = atomicAdd(&cnt[d], 1);
    if (p < SLOTS) srcs[(size_t)d * SLOTS + p] = __ldg(&src[e]);
}

__global__ void dinv_kernel(const int* ca, const int* cb, float* da, float* db, int n) {
    int i = blockIdx.x * blockDim.x + threadIdx.x;
    if (i < n) {
        da[i] = rsqrtf((float)ca[i] + 1.0f);
        db[i] = rsqrtf((float)cb[i] + 1.0f);
    }
}

// mark S = roots ∪ {bucket srcs of roots}; thread per (root, slot), slot 64 = root
__global__ void mark_kernel(const int* __restrict__ roots,
                            const int* __restrict__ cnt0, const int* __restrict__ srcs0,
                            const int* __restrict__ cnt1, const int* __restrict__ srcs1,
                            char* mark0, char* mark1, int R) {
    int idx = blockIdx.x * blockDim.x + threadIdx.x;
    if (idx >= R * 65) return;
    int r = idx / 65;
    int s = idx % 65;
    const int* cnt; const int* srcs; char* mark;
    if (blockIdx.y) { cnt = cnt1; srcs = srcs1; mark = mark1; }
    else            { cnt = cnt0; srcs = srcs0; mark = mark0; }
    int node = __ldg(&roots[r]);
    if (s == 64) { mark[node] = 1; return; }
    int c = min(__ldg(&cnt[node]), SLOTS);
    if (s < c) mark[__ldg(&srcs[(size_t)node * SLOTS + s])] = 1;
}

__global__ void compact_kernel(const char* __restrict__ mark0, const char* __restrict__ mark1,
                               int* __restrict__ list0, int* __restrict__ list1,
                               int* listcnt, int N) {
    int i = blockIdx.x * blockDim.x + threadIdx.x;
    if (i >= N) return;
    const char* mark; int* list; int b = blockIdx.y;
    if (b) { mark = mark1; list = list1; }
    else   { mark = mark0; list = list0; }
    if (mark[i]) {
        int p = atomicAdd(&listcnt[b], 1);
        list[p] = i;
    }
}

// ---------------- fp16 mma helpers ----------------

__device__ __forceinline__ void mma_f16(float* c, const uint32_t* a, const uint32_t* b) {
    asm volatile(
        "mma.sync.aligned.m16n8k16.row.col.f32.f16.f16.f32 "
        "{%0,%1,%2,%3}, {%4,%5,%6,%7}, {%8,%9}, {%0,%1,%2,%3};"
        : "+f"(c[0]), "+f"(c[1]), "+f"(c[2]), "+f"(c[3])
        : "r"(a[0]), "r"(a[1]), "r"(a[2]), "r"(a[3]),
          "r"(b[0]), "r"(b[1]));
}

__device__ __forceinline__ int sw_idx(int k, int m) {
    return k * 136 + (m ^ (((k >> 2) & 3) << 3));
}

__device__ __forceinline__ float elu1(float x) {
    return x > 0.f ? x : expm1f(x);
}

// ---------------- GEMM: Y[M,128] = epi(X[M,K] @ W[K,128]) ----------------
// EPI=0: Y = D[row] * acc           (A' for aggregation)
// EPI=1: Y = elu(bias[col] + acc)   (layer-2 root output)

template <int K, int EPI>
__global__ __launch_bounds__(256, 2)
void gemm_tc(const uint32_t* __restrict__ X, const uint32_t* __restrict__ W,
             uint32_t* __restrict__ Y, const float* __restrict__ D,
             const float* __restrict__ bias, int M) {
    constexpr int K2 = K / 2;
    constexpr int NC = K / 32;

    __shared__ uint32_t xs[2][16 * 136];
    __shared__ uint32_t ws[2][16 * 136];

    const int tid  = threadIdx.x;
    const int lane = tid & 31;
    const int wid  = tid >> 5;
    const int g    = lane >> 2;
    const int tig  = lane & 3;
    const int mbase = (wid & 1) * 64;
    const int nbase = (wid >> 1) * 32;
    const int row0  = blockIdx.x * 128;

    const int xr  = tid >> 2;
    const int xkq = (tid & 3) * 4;
    const int wkr = tid >> 5;
    const int wcq = (tid & 31) * 4;

    float c[4][4][4];
#pragma unroll
    for (int mf = 0; mf < 4; mf++)
#pragma unroll
        for (int nf = 0; nf < 4; nf++)
#pragma unroll
            for (int q = 0; q < 4; q++) c[mf][nf][q] = 0.f;

    uint4 xv[2], wv[2];

    auto loadg = [&](int t) {
        const int p0 = t * 16;
#pragma unroll
        for (int l = 0; l < 2; l++) {
            int r = xr + l * 64;
            int grow = row0 + r;
            xv[l] = (grow < M) ? *(const uint4*)&X[(size_t)grow * K2 + p0 + xkq]
                               : make_uint4(0u, 0u, 0u, 0u);
            wv[l] = *(const uint4*)&W[(size_t)(p0 + wkr + l * 8) * 128 + wcq];
        }
    };
    auto store_s = [&](int buf) {
#pragma unroll
        for (int l = 0; l < 2; l++) {
            int r = xr + l * 64;
            xs[buf][sw_idx(xkq + 0, r)] = xv[l].x;
            xs[buf][sw_idx(xkq + 1, r)] = xv[l].y;
            xs[buf][sw_idx(xkq + 2, r)] = xv[l].z;
            xs[buf][sw_idx(xkq + 3, r)] = xv[l].w;
            *(uint4*)&ws[buf][sw_idx(wkr + l * 8, wcq)] = wv[l];
        }
    };
    auto compute = [&](int buf) {
#pragma unroll
        for (int ks = 0; ks < 2; ks++) {
            const int klo = ks * 8 + tig;
            const int khi = klo + 4;
            uint32_t a[4][4], b[4][2];
#pragma unroll
            for (int mf = 0; mf < 4; mf++) {
                int m0 = mbase + mf * 16 + g;
                a[mf][0] = xs[buf][sw_idx(klo, m0)];
                a[mf][1] = xs[buf][sw_idx(klo, m0 + 8)];
                a[mf][2] = xs[buf][sw_idx(khi, m0)];
                a[mf][3] = xs[buf][sw_idx(khi, m0 + 8)];
            }
#pragma unroll
            for (int nf = 0; nf < 4; nf++) {
                int n0 = nbase + nf * 8 + g;
                b[nf][0] = ws[buf][sw_idx(klo, n0)];
                b[nf][1] = ws[buf][sw_idx(khi, n0)];
            }
#pragma unroll
            for (int mf = 0; mf < 4; mf++)
#pragma unroll
                for (int nf = 0; nf < 4; nf++)
                    mma_f16(c[mf][nf], a[mf], b[nf]);
        }
    };

    loadg(0);
    store_s(0);
    __syncthreads();

    for (int t = 0; t < NC; t++) {
        if (t + 1 < NC) loadg(t + 1);
        compute(t & 1);
        if (t + 1 < NC) {
            store_s((t + 1) & 1);
            __syncthreads();
        }
    }

#pragma unroll
    for (int mf = 0; mf < 4; mf++) {
        int r0 = row0 + mbase + mf * 16 + g;
        float dlo = 0.f, dhi = 0.f;
        if (EPI == 0) {
            dlo = (r0 < M)     ? __ldg(&D[r0])     : 0.f;
            dhi = (r0 + 8 < M) ? __ldg(&D[r0 + 8]) : 0.f;
        }
#pragma unroll
        for (int nf = 0; nf < 4; nf++) {
            int ncol = nbase + nf * 8 + tig * 2;
            int np = ncol >> 1;
            if (EPI == 0) {
                if (r0 < M)
                    Y[(size_t)r0 * 64 + np] =
                        h2_u32(__floats2half2_rn(dlo * c[mf][nf][0], dlo * c[mf][nf][1]));
                if (r0 + 8 < M)
                    Y[(size_t)(r0 + 8) * 64 + np] =
                        h2_u32(__floats2half2_rn(dhi * c[mf][nf][2], dhi * c[mf][nf][3]));
            } else {
                float b0 = __ldg(&bias[ncol]);
                float b1 = __ldg(&bias[ncol + 1]);
                if (r0 < M)
                    Y[(size_t)r0 * 64 + np] =
                        h2_u32(__floats2half2_rn(elu1(b0 + c[mf][nf][0]),
                                                 elu1(b1 + c[mf][nf][1])));
                if (r0 + 8 < M)
                    Y[(size_t)(r0 + 8) * 64 + np] =
                        h2_u32(__floats2half2_rn(elu1(b0 + c[mf][nf][2]),
                                                 elu1(b1 + c[mf][nf][3])));
            }
        }
    }
}

// ---------------- layer-1 aggregation restricted to S (list) ----------------
// B1s[node] = dinv[node] * elu(bias + dinv[node] * (sum A'[src] + A'[node]))

__global__ __launch_bounds__(256)
void agg_list(const uint32_t* __restrict__ A, uint32_t* __restrict__ B,
              const int* __restrict__ cnt, const int* __restrict__ srcs,
              const float* __restrict__ dinv, const float* __restrict__ bias,
              const int* __restrict__ list, const int* __restrict__ listcnt) {
    int idx = (blockIdx.x * 256 + threadIdx.x) >> 5;
    if (idx >= *listcnt) return;
    int node = __ldg(&list[idx]);
    int lane = threadIdx.x & 31;

    const uint2* A2 = (const uint2*)A;
    float4 acc = h4_to_f4(A2[(size_t)node * 32 + lane]);   // self loop

    int c = min(__ldg(&cnt[node]), SLOTS);
    const int* sp = &srcs[(size_t)node * SLOTS];

    int i = 0;
    for (; i + 4 <= c; i += 4) {
        int4 s4 = *(const int4*)&sp[i];
        float4 v0 = h4_to_f4(__ldg(&A2[(size_t)s4.x * 32 + lane]));
        float4 v1 = h4_to_f4(__ldg(&A2[(size_t)s4.y * 32 + lane]));
        float4 v2 = h4_to_f4(__ldg(&A2[(size_t)s4.z * 32 + lane]));
        float4 v3 = h4_to_f4(__ldg(&A2[(size_t)s4.w * 32 + lane]));
        acc.x += v0.x + v1.x + v2.x + v3.x;
        acc.y += v0.y + v1.y + v2.y + v3.y;
        acc.z += v0.z + v1.z + v2.z + v3.z;
        acc.w += v0.w + v1.w + v2.w + v3.w;
    }
    for (; i < c; i++) {
        int s = __ldg(&sp[i]);
        float4 v = h4_to_f4(__ldg(&A2[(size_t)s * 32 + lane]));
        acc.x += v.x; acc.y += v.y; acc.z += v.z; acc.w += v.w;
    }

    const float dd = __ldg(&dinv[node]);
    float4 bv = *(const float4*)&bias[lane * 4];
    acc.x = dd * elu1(fmaf(dd, acc.x, bv.x));
    acc.y = dd * elu1(fmaf(dd, acc.y, bv.y));
    acc.z = dd * elu1(fmaf(dd, acc.z, bv.z));
    acc.w = dd * elu1(fmaf(dd, acc.w, bv.w));

    uint2 o;
    o.x = h2_u32(__floats2half2_rn(acc.x, acc.y));
    o.y = h2_u32(__floats2half2_rn(acc.z, acc.w));
    ((uint2*)B)[(size_t)node * 32 + lane] = o;
}

// ---------------- layer-2 gather at roots ----------------
// g[r] = dinv[root] * (B1s[root] + sum_bucket B1s[s])   (fp16 out)

__global__ __launch_bounds__(256)
void gather2_kernel(const uint32_t* __restrict__ B,
                    const int* __restrict__ roots,
                    const int* __restrict__ cnt, const int* __restrict__ srcs,
                    const float* __restrict__ dinv,
                    uint32_t* __restrict__ gbuf, int R) {
    int r = blockIdx.x * 8 + (threadIdx.x >> 5);
    if (r >= R) return;
    int lane = threadIdx.x & 31;
    int node = __ldg(&roots[r]);

    const uint2* B2 = (const uint2*)B;
    float4 acc = h4_to_f4(B2[(size_t)node * 32 + lane]);   // self

    int c = min(__ldg(&cnt[node]), SLOTS);
    const int* sp = &srcs[(size_t)node * SLOTS];
    for (int i = 0; i < c; i++) {
        int s = __ldg(&sp[i]);
        float4 v = h4_to_f4(__ldg(&B2[(size_t)s * 32 + lane]));
        acc.x += v.x; acc.y += v.y; acc.z += v.z; acc.w += v.w;
    }

    float dd = __ldg(&dinv[node]);
    uint2 o;
    o.x = h2_u32(__floats2half2_rn(dd * acc.x, dd * acc.y));
    o.y = h2_u32(__floats2half2_rn(dd * acc.z, dd * acc.w));
    ((uint2*)gbuf)[(size_t)r * 32 + lane] = o;
}

// ---------------- fused head: fc + log_softmax over root features -----------

__global__ __launch_bounds__(256)
void head_kernel(const uint32_t* __restrict__ Rtd, const uint32_t* __restrict__ Rbu,
                 const float* __restrict__ fcw, const float* __restrict__ fcb,
                 float* __restrict__ out, int R) {
    int r = blockIdx.x * 8 + (threadIdx.x >> 5);
    if (r >= R) return;
    int lane = threadIdx.x & 31;

    float4 ftd = h4_to_f4(((const uint2*)Rtd)[(size_t)r * 32 + lane]);
    float4 fbu = h4_to_f4(((const uint2*)Rbu)[(size_t)r * 32 + lane]);

    float s0 = 0.f, s1 = 0.f, s2 = 0.f, s3 = 0.f;
    const float* ft = &ftd.x;
    const float* fb = &fbu.x;
#pragma unroll
    for (int j = 0; j < 4; j++) {
        int k = lane * 4 + j;
        float4 wt = *(const float4*)&fcw[(size_t)k * 4];
        float4 wb = *(const float4*)&fcw[(size_t)(128 + k) * 4];
        s0 = fmaf(ft[j], wt.x, fmaf(fb[j], wb.x, s0));
        s1 = fmaf(ft[j], wt.y, fmaf(fb[j], wb.y, s1));
        s2 = fmaf(ft[j], wt.z, fmaf(fb[j], wb.z, s2));
        s3 = fmaf(ft[j], wt.w, fmaf(fb[j], wb.w, s3));
    }
#pragma unroll
    for (int off = 16; off; off >>= 1) {
        s0 += __shfl_xor_sync(0xffffffffu, s0, off);
        s1 += __shfl_xor_sync(0xffffffffu, s1, off);
        s2 += __shfl_xor_sync(0xffffffffu, s2, off);
        s3 += __shfl_xor_sync(0xffffffffu, s3, off);
    }
    if (lane == 0) {
        s0 += fcb[0]; s1 += fcb[1]; s2 += fcb[2]; s3 += fcb[3];
        float m = fmaxf(fmaxf(s0, s1), fmaxf(s2, s3));
        float s = expf(s0 - m) + expf(s1 - m) + expf(s2 - m) + expf(s3 - m);
        float lse = m + logf(s);
        float4 o = make_float4(s0 - lse, s1 - lse, s2 - lse, s3 - lse);
        *(float4*)&out[(size_t)r * 4] = o;
    }
}

// ---------------------------------------------------------------------------

extern "C" void kernel_launch(void* const* d_in, const int* in_sizes, int n_in,
                              void* d_out, int out_size) {
    const float* x       = (const float*)d_in[0];
    const int*   ei_td   = (const int*)d_in[1];
    const int*   ei_bu   = (const int*)d_in[2];
    const int*   rootidx = (const int*)d_in[3];
    const float* w1 = (const float*)d_in[4];
    const float* b1 = (const float*)d_in[5];
    const float* w2 = (const float*)d_in[6];
    const float* b2 = (const float*)d_in[7];
    const float* w3 = (const float*)d_in[8];
    const float* b3 = (const float*)d_in[9];
    const float* w4 = (const float*)d_in[10];
    const float* b4 = (const float*)d_in[11];
    const float* fcw = (const float*)d_in[12];
    const float* fcb = (const float*)d_in[13];
    float* out = (float*)d_out;

    const int N = in_sizes[0] / 256;
    const int E = in_sizes[1] / 2;
    const int R = in_sizes[3];

    const int* src_td = ei_td;
    const int* dst_td = ei_td + E;
    const int* src_bu = ei_bu;
    const int* dst_bu = ei_bu + E;

    uint32_t *A_td, *B_td, *A_bu, *B_bu, *xh, *wh, *g_td, *g_bu, *r_td, *r_bu;
    float *dinv_td, *dinv_bu;
    int *cnt_td, *cnt_bu, *srcs_td, *srcs_bu, *list_td, *list_bu, *listcnt;
    char *mark_td, *mark_bu;
    cudaGetSymbolAddress((void**)&A_td, g_A_td);
    cudaGetSymbolAddress((void**)&B_td, g_B_td);
    cudaGetSymbolAddress((void**)&A_bu, g_A_bu);
    cudaGetSymbolAddress((void**)&B_bu, g_B_bu);
    cudaGetSymbolAddress((void**)&xh, g_xh);
    cudaGetSymbolAddress((void**)&wh, g_wh);
    cudaGetSymbolAddress((void**)&cnt_td, g_cnt_td);
    cudaGetSymbolAddress((void**)&cnt_bu, g_cnt_bu);
    cudaGetSymbolAddress((void**)&dinv_td, g_dinv_td);
    cudaGetSymbolAddress((void**)&dinv_bu, g_dinv_bu);
    cudaGetSymbolAddress((void**)&srcs_td, g_srcs_td);
    cudaGetSymbolAddress((void**)&srcs_bu, g_srcs_bu);
    cudaGetSymbolAddress((void**)&mark_td, g_mark_td);
    cudaGetSymbolAddress((void**)&mark_bu, g_mark_bu);
    cudaGetSymbolAddress((void**)&list_td, g_list_td);
    cudaGetSymbolAddress((void**)&list_bu, g_list_bu);
    cudaGetSymbolAddress((void**)&listcnt, g_listcnt);
    cudaGetSymbolAddress((void**)&g_td, g_g_td);
    cudaGetSymbolAddress((void**)&g_bu, g_g_bu);
    cudaGetSymbolAddress((void**)&r_td, g_r_td);
    cudaGetSymbolAddress((void**)&r_bu, g_r_bu);

    const uint32_t* w1h = wh;
    const uint32_t* w2h = wh + 128 * 128;
    const uint32_t* w3h = wh + 192 * 128;
    const uint32_t* w4h = wh + 320 * 128;

    static cudaStream_t sB = nullptr, sC = nullptr;
    static cudaEvent_t evFork, evXh, evPrep, evWh, evBuDone;
    if (!sB) {
        cudaStreamCreateWithFlags(&sB, cudaStreamNonBlocking);
        cudaStreamCreateWithFlags(&sC, cudaStreamNonBlocking);
        cudaEventCreateWithFlags(&evFork,  cudaEventDisableTiming);
        cudaEventCreateWithFlags(&evXh,    cudaEventDisableTiming);
        cudaEventCreateWithFlags(&evPrep,  cudaEventDisableTiming);
        cudaEventCreateWithFlags(&evWh,    cudaEventDisableTiming);
        cudaEventCreateWithFlags(&evBuDone,cudaEventDisableTiming);
    }
    cudaStream_t sA = 0;

    const int gemm_blocks = ceil_div(N, 128);
    const int agg_blocks  = ceil_div(N, 8);      // upper bound; early-exit on listcnt
    const int root_gemm_blocks = ceil_div(R, 128);

    // fork
    cudaEventRecord(evFork, sA);
    cudaStreamWaitEvent(sB, evFork, 0);
    cudaStreamWaitEvent(sC, evFork, 0);

    // sA: convert x
    convert_x_kernel<<<ceil_div(N * 64, 256), 256, 0, sA>>>(x, xh, N * 64);
    cudaEventRecord(evXh, sA);

    // sB: zero -> fill -> dinv -> mark -> compact
    zero_kernel<<<ceil_div(N, 256), 256, 0, sB>>>(cnt_td, cnt_bu, mark_td, mark_bu, listcnt, N);
    fill_kernel<<<dim3(ceil_div(E, 256), 2), 256, 0, sB>>>(
        src_td, dst_td, src_bu, dst_bu, cnt_td, cnt_bu, srcs_td, srcs_bu, E);
    dinv_kernel<<<ceil_div(N, 256), 256, 0, sB>>>(cnt_td, cnt_bu, dinv_td, dinv_bu, N);
    mark_kernel<<<dim3(ceil_div(R * 65, 256), 2), 256, 0, sB>>>(
        rootidx, cnt_td, srcs_td, cnt_bu, srcs_bu, mark_td, mark_bu, R);
    compact_kernel<<<dim3(ceil_div(N, 256), 2), 256, 0, sB>>>(
        mark_td, mark_bu, list_td, list_bu, listcnt, N);
    cudaEventRecord(evPrep, sB);

    // sC: pack weights
    pack_w_kernel<<<192, 256, 0, sC>>>(w1, w2, w3, w4, wh);
    cudaEventRecord(evWh, sC);

    // --- td branch on sA ---
    cudaStreamWaitEvent(sA, evPrep, 0);
    cudaStreamWaitEvent(sA, evWh, 0);
    gemm_tc<256, 0><<<gemm_blocks, 256, 0, sA>>>(xh, w1h, A_td, dinv_td, b1, N);
    agg_list<<<agg_blocks, 256, 0, sA>>>(A_td, B_td, cnt_td, srcs_td, dinv_td, b1,
                                         list_td, &listcnt[0]);
    gather2_kernel<<<ceil_div(R, 8), 256, 0, sA>>>(B_td, rootidx, cnt_td, srcs_td,
                                                   dinv_td, g_td, R);
    gemm_tc<128, 1><<<root_gemm_blocks, 256, 0, sA>>>(g_td, w2h, r_td, dinv_td, b2, R);

    // --- bu branch on sB ---
    cudaStreamWaitEvent(sB, evXh, 0);
    cudaStreamWaitEvent(sB, evWh, 0);
    gemm_tc<256, 0><<<gemm_blocks, 256, 0, sB>>>(xh, w3h, A_bu, dinv_bu, b3, N);
    agg_list<<<agg_blocks, 256, 0, sB>>>(A_bu, B_bu, cnt_bu, srcs_bu, dinv_bu, b3,
                                         list_bu, &listcnt[1]);
    gather2_kernel<<<ceil_div(R, 8), 256, 0, sB>>>(B_bu, rootidx, cnt_bu, srcs_bu,
                                                   dinv_bu, g_bu, R);
    gemm_tc<128, 1><<<root_gemm_blocks, 256, 0, sB>>>(g_bu, w4h, r_bu, dinv_bu, b4, R);
    cudaEventRecord(evBuDone, sB);

    // join + head
    cudaStreamWaitEvent(sA, evBuDone, 0);
    head_kernel<<<ceil_div(R, 8), 256, 0, sA>>>(r_td, r_bu, fcw, fcb, out, R);
}